// round 5
// baseline (speedup 1.0000x reference)
#include <cuda_runtime.h>
#include <math.h>

#define D_MODEL 1024
#define N_HEAD  16
#define D_HEAD  64
#define N_CTX   2048
#define BATCH   2
#define M_TOTAL (BATCH * N_CTX)   /* 4096 rows */

// Scratch (allocation-guard-safe device globals)
__device__ float g_q[(size_t)M_TOTAL * D_MODEL];
__device__ float g_k[(size_t)M_TOTAL * D_MODEL];
__device__ float g_v[(size_t)M_TOTAL * D_MODEL];
__device__ float g_z[(size_t)M_TOTAL * D_MODEL];
__device__ float g_cos[N_CTX * 32];
__device__ float g_sin[N_CTX * 32];

// ---------------------------------------------------------------------------
// RoPE table: accurate fp64 trig of the fp32-rounded angle (matches the
// reference's fp32 outer(t, inv_freq) then cos/sin). Immune to fast-math.
// ---------------------------------------------------------------------------
__global__ void rope_table_kernel()
{
    int j = threadIdx.x;        // 0..31 (frequency index)
    int s = blockIdx.x;         // 0..2047 (position)
    float inv_freq = (float)pow(10000.0, -(double)j / 32.0);
    float a = (float)s * inv_freq;           // fp32 rounding, like reference
    double sd, cd;
    sincos((double)a, &sd, &cd);             // fp64: correct range reduction
    g_cos[s * 32 + j] = (float)cd;
    g_sin[s * 32 + j] = (float)sd;
}

// ---------------------------------------------------------------------------
// NT GEMM: C[m,n] = sum_k A[m,k] * W[n,k]  (+ bias[n]) (+ add[m,n])
// Tiles: BM=BN=64, BK=16, 256 threads, 4x4 per thread.
// ---------------------------------------------------------------------------
template <bool HAS_BIAS, bool HAS_ADD>
__global__ void __launch_bounds__(256)
gemm_nt_kernel(const float* __restrict__ A, const float* __restrict__ W,
               const float* __restrict__ bias, const float* __restrict__ add,
               float* __restrict__ C, int M, int N, int K)
{
    __shared__ float As[16][64];   // [k][m]
    __shared__ float Bs[16][64];   // [k][n]

    const int tid = threadIdx.x;
    const int tx  = tid & 15;        // n sub-tile
    const int ty  = tid >> 4;        // m sub-tile
    const int m0  = blockIdx.y * 64;
    const int n0  = blockIdx.x * 64;

    const int lrow = tid >> 2;       // 0..63
    const int lk4  = (tid & 3) * 4;  // 0,4,8,12

    float acc[4][4] = {};

    for (int kt = 0; kt < K; kt += 16) {
        float4 av = *(const float4*)&A[(size_t)(m0 + lrow) * K + kt + lk4];
        float4 wv = *(const float4*)&W[(size_t)(n0 + lrow) * K + kt + lk4];
        __syncthreads();
        As[lk4 + 0][lrow] = av.x; As[lk4 + 1][lrow] = av.y;
        As[lk4 + 2][lrow] = av.z; As[lk4 + 3][lrow] = av.w;
        Bs[lk4 + 0][lrow] = wv.x; Bs[lk4 + 1][lrow] = wv.y;
        Bs[lk4 + 2][lrow] = wv.z; Bs[lk4 + 3][lrow] = wv.w;
        __syncthreads();

        #pragma unroll
        for (int kk = 0; kk < 16; kk++) {
            float4 a = *(const float4*)&As[kk][ty * 4];
            float4 b = *(const float4*)&Bs[kk][tx * 4];
            acc[0][0] += a.x * b.x; acc[0][1] += a.x * b.y;
            acc[0][2] += a.x * b.z; acc[0][3] += a.x * b.w;
            acc[1][0] += a.y * b.x; acc[1][1] += a.y * b.y;
            acc[1][2] += a.y * b.z; acc[1][3] += a.y * b.w;
            acc[2][0] += a.z * b.x; acc[2][1] += a.z * b.y;
            acc[2][2] += a.z * b.z; acc[2][3] += a.z * b.w;
            acc[3][0] += a.w * b.x; acc[3][1] += a.w * b.y;
            acc[3][2] += a.w * b.z; acc[3][3] += a.w * b.w;
        }
    }

    float4 bv = make_float4(0.f, 0.f, 0.f, 0.f);
    if (HAS_BIAS) bv = *(const float4*)&bias[n0 + tx * 4];

    #pragma unroll
    for (int i = 0; i < 4; i++) {
        int row = m0 + ty * 4 + i;
        float4 o;
        o.x = acc[i][0] + bv.x; o.y = acc[i][1] + bv.y;
        o.z = acc[i][2] + bv.z; o.w = acc[i][3] + bv.w;
        if (HAS_ADD) {
            float4 xv = *(const float4*)&add[(size_t)row * N + n0 + tx * 4];
            o.x += xv.x; o.y += xv.y; o.z += xv.z; o.w += xv.w;
        }
        *(float4*)&C[(size_t)row * N + n0 + tx * 4] = o;
    }
}

// ---------------------------------------------------------------------------
// RMSNorm (per head, Dh=64, eps=FLT_EPSILON) + RoPE (in-place).
// One warp per (b*s, h) row. Lane i owns elements (2i, 2i+1).
// ---------------------------------------------------------------------------
__global__ void __launch_bounds__(256)
norm_rope_kernel(float* __restrict__ buf, const float* __restrict__ norm_w)
{
    int gwarp = (blockIdx.x * blockDim.x + threadIdx.x) >> 5;
    int lane  = threadIdx.x & 31;
    if (gwarp >= M_TOTAL * N_HEAD) return;

    int m = gwarp >> 4;          // 0..4095 (b*S + s)
    int h = gwarp & 15;
    int s = m & (N_CTX - 1);     // position within sequence

    float* p = buf + (size_t)m * D_MODEL + h * D_HEAD;
    float2 x = *(float2*)(p + 2 * lane);

    float ss = x.x * x.x + x.y * x.y;
    #pragma unroll
    for (int off = 16; off > 0; off >>= 1)
        ss += __shfl_xor_sync(0xFFFFFFFFu, ss, off);

    float r = rsqrtf(ss * (1.0f / 64.0f) + 1.1920929e-07f);

    int d0 = 2 * lane, d1 = 2 * lane + 1;
    float xn0 = x.x * r * norm_w[d0];
    float xn1 = x.y * r * norm_w[d1];

    int j0 = d0 & 31, j1 = d1 & 31;
    float c0 = g_cos[s * 32 + j0], s0 = g_sin[s * 32 + j0];
    float c1 = g_cos[s * 32 + j1], s1 = g_sin[s * 32 + j1];

    // out[2i]   = xn[2i]*cos(a0) - xn[2i+1]*sin(a0)
    // out[2i+1] = xn[2i+1]*cos(a1) + xn[2i]*sin(a1)
    float o0 = xn0 * c0 - xn1 * s0;
    float o1 = xn1 * c1 + xn0 * s1;
    *(float2*)(p + 2 * lane) = make_float2(o0, o1);
}

// ---------------------------------------------------------------------------
// Fused quadratic attention (no softmax):
//   z[q,:] = sum_{k<=q} (q.k / 64)^2 * v[k,:]
// One CTA per (query tile of 64, b*h). 256 threads, 4x4 register tiles.
// Shared: Qs [d][q], Ks [d][k] (reused as Ssq [k][q]), Vs [k][d] = 48 KB.
// ---------------------------------------------------------------------------
__global__ void __launch_bounds__(256)
attn_kernel()
{
    __shared__ float Qs[64][64];   // [d][q]
    __shared__ float Ks[64][64];   // [d][k], reused as Ssq[k][q]
    __shared__ float Vs[64][64];   // [k][d]

    const int qt = blockIdx.x;     // 0..31
    const int bh = blockIdx.y;     // 0..31
    const int b  = bh >> 4;
    const int h  = bh & 15;

    const float* Qg = g_q + (size_t)b * N_CTX * D_MODEL + h * D_HEAD;
    const float* Kg = g_k + (size_t)b * N_CTX * D_MODEL + h * D_HEAD;
    const float* Vg = g_v + (size_t)b * N_CTX * D_MODEL + h * D_HEAD;

    const int tid = threadIdx.x;
    const int tx  = tid & 15;
    const int ty  = tid >> 4;

    // Load Q tile transposed: Qs[d][q]
    #pragma unroll
    for (int r = 0; r < 4; r++) {
        int idx = tid + r * 256;       // 0..1023
        int row = idx >> 4;            // 0..63
        int d4  = (idx & 15) * 4;
        float4 v = *(const float4*)&Qg[(size_t)(qt * 64 + row) * D_MODEL + d4];
        Qs[d4 + 0][row] = v.x; Qs[d4 + 1][row] = v.y;
        Qs[d4 + 2][row] = v.z; Qs[d4 + 3][row] = v.w;
    }

    float zacc[4][4] = {};

    for (int kt = 0; kt <= qt; kt++) {
        __syncthreads();  // previous iter done with Ks(Ssq)/Vs; Qs writes drained (kt=0)

        #pragma unroll
        for (int r = 0; r < 4; r++) {
            int idx = tid + r * 256;
            int row = idx >> 4;
            int d4  = (idx & 15) * 4;
            float4 kv = *(const float4*)&Kg[(size_t)(kt * 64 + row) * D_MODEL + d4];
            Ks[d4 + 0][row] = kv.x;
            Ks[d4 + 1][row] = kv.y;
            Ks[d4 + 2][row] = kv.z;
            Ks[d4 + 3][row] = kv.w;
            float4 vv = *(const float4*)&Vg[(size_t)(kt * 64 + row) * D_MODEL + d4];
            *(float4*)&Vs[row][d4] = vv;
        }
        __syncthreads();

        // S tile = Q . K^T (this thread: rows ty*4+i, cols tx*4+j)
        float sacc[4][4] = {};
        #pragma unroll 8
        for (int d = 0; d < 64; d++) {
            float4 qa = *(const float4*)&Qs[d][ty * 4];
            float4 kb = *(const float4*)&Ks[d][tx * 4];
            sacc[0][0] += qa.x * kb.x; sacc[0][1] += qa.x * kb.y;
            sacc[0][2] += qa.x * kb.z; sacc[0][3] += qa.x * kb.w;
            sacc[1][0] += qa.y * kb.x; sacc[1][1] += qa.y * kb.y;
            sacc[1][2] += qa.y * kb.z; sacc[1][3] += qa.y * kb.w;
            sacc[2][0] += qa.z * kb.x; sacc[2][1] += qa.z * kb.y;
            sacc[2][2] += qa.z * kb.z; sacc[2][3] += qa.z * kb.w;
            sacc[3][0] += qa.w * kb.x; sacc[3][1] += qa.w * kb.y;
            sacc[3][2] += qa.w * kb.z; sacc[3][3] += qa.w * kb.w;
        }
        __syncthreads();  // everyone done reading Ks

        // pattern = (S/64)^2 * causal ; stage into Ks as Ssq[k][q]
        #pragma unroll
        for (int i = 0; i < 4; i++) {
            int qg = qt * 64 + ty * 4 + i;
            #pragma unroll
            for (int j = 0; j < 4; j++) {
                int kg = kt * 64 + tx * 4 + j;
                float p = sacc[i][j] * (1.0f / 64.0f);
                p = p * p;
                if (kg > qg) p = 0.0f;
                Ks[tx * 4 + j][ty * 4 + i] = p;
            }
        }
        __syncthreads();

        // Z += Ssq^T-view @ V  (zacc rows=q, cols=d)
        #pragma unroll 8
        for (int kk = 0; kk < 64; kk++) {
            float4 sa = *(const float4*)&Ks[kk][ty * 4];
            float4 vb = *(const float4*)&Vs[kk][tx * 4];
            zacc[0][0] += sa.x * vb.x; zacc[0][1] += sa.x * vb.y;
            zacc[0][2] += sa.x * vb.z; zacc[0][3] += sa.x * vb.w;
            zacc[1][0] += sa.y * vb.x; zacc[1][1] += sa.y * vb.y;
            zacc[1][2] += sa.y * vb.z; zacc[1][3] += sa.y * vb.w;
            zacc[2][0] += sa.z * vb.x; zacc[2][1] += sa.z * vb.y;
            zacc[2][2] += sa.z * vb.z; zacc[2][3] += sa.z * vb.w;
            zacc[3][0] += sa.w * vb.x; zacc[3][1] += sa.w * vb.y;
            zacc[3][2] += sa.w * vb.z; zacc[3][3] += sa.w * vb.w;
        }
    }

    float* Zg = g_z + (size_t)b * N_CTX * D_MODEL + h * D_HEAD;
    #pragma unroll
    for (int i = 0; i < 4; i++) {
        float4 o = make_float4(zacc[i][0], zacc[i][1], zacc[i][2], zacc[i][3]);
        *(float4*)&Zg[(size_t)(qt * 64 + ty * 4 + i) * D_MODEL + tx * 4] = o;
    }
}

// ---------------------------------------------------------------------------
// Launch
// ---------------------------------------------------------------------------
extern "C" void kernel_launch(void* const* d_in, const int* in_sizes, int n_in,
                              void* d_out, int out_size)
{
    const float* x      = (const float*)d_in[0];
    const float* Wq     = (const float*)d_in[1];
    const float* bq     = (const float*)d_in[2];
    const float* Wk     = (const float*)d_in[3];
    const float* bk     = (const float*)d_in[4];
    const float* Wv     = (const float*)d_in[5];
    const float* bv     = (const float*)d_in[6];
    const float* Wo     = (const float*)d_in[7];
    const float* norm_w = (const float*)d_in[8];
    float* out          = (float*)d_out;

    float *q, *k, *v, *z;
    cudaGetSymbolAddress((void**)&q, g_q);
    cudaGetSymbolAddress((void**)&k, g_k);
    cudaGetSymbolAddress((void**)&v, g_v);
    cudaGetSymbolAddress((void**)&z, g_z);

    dim3 gdim(D_MODEL / 64, M_TOTAL / 64);  // (16, 64)
    dim3 bdim(256);

    // RoPE cos/sin table (fp64 trig, fast-math-proof)
    rope_table_kernel<<<N_CTX, 32>>>();

    // QKV projections with bias
    gemm_nt_kernel<true, false><<<gdim, bdim>>>(x, Wq, bq, nullptr, q,
                                                M_TOTAL, D_MODEL, D_MODEL);
    gemm_nt_kernel<true, false><<<gdim, bdim>>>(x, Wk, bk, nullptr, k,
                                                M_TOTAL, D_MODEL, D_MODEL);
    gemm_nt_kernel<true, false><<<gdim, bdim>>>(x, Wv, bv, nullptr, v,
                                                M_TOTAL, D_MODEL, D_MODEL);

    // RMSNorm + RoPE on q and k (in-place)
    int nwarps = M_TOTAL * N_HEAD;                 // 65536
    int nblocks = nwarps / 8;                      // 256 threads = 8 warps
    norm_rope_kernel<<<nblocks, 256>>>(q, norm_w);
    norm_rope_kernel<<<nblocks, 256>>>(k, norm_w);

    // Fused quadratic attention -> z
    attn_kernel<<<dim3(N_CTX / 64, BATCH * N_HEAD), 256>>>();

    // out = x + z @ Wo^T
    gemm_nt_kernel<false, true><<<gdim, bdim>>>(z, Wo, nullptr, x, out,
                                                M_TOTAL, D_MODEL, D_MODEL);
}

// round 8
// speedup vs baseline: 1.9779x; 1.9779x over previous
#include <cuda_runtime.h>
#include <math.h>

#define D_MODEL 1024
#define N_HEAD  16
#define D_HEAD  64
#define N_CTX   2048
#define BATCH   2
#define M_TOTAL (BATCH * N_CTX)   /* 4096 rows */

__device__ float g_q[(size_t)M_TOTAL * D_MODEL];
__device__ float g_k[(size_t)M_TOTAL * D_MODEL];
__device__ float g_v[(size_t)M_TOTAL * D_MODEL];
__device__ float g_z[(size_t)M_TOTAL * D_MODEL];
__device__ float g_cos[N_CTX * 32];
__device__ float g_sin[N_CTX * 32];

// ---------------------------------------------------------------------------
// RoPE table: fp64 trig of the fp32-rounded angle (fast-math-proof).
// ---------------------------------------------------------------------------
__global__ void rope_table_kernel()
{
    int j = threadIdx.x;        // 0..31
    int s = blockIdx.x;         // 0..2047
    float inv_freq = (float)pow(10000.0, -(double)j / 32.0);
    float a = (float)s * inv_freq;
    double sd, cd;
    sincos((double)a, &sd, &cd);
    g_cos[s * 32 + j] = (float)cd;
    g_sin[s * 32 + j] = (float)sd;
}

// ---------------------------------------------------------------------------
// NT GEMM v2: C[m,n] = sum_k A[m,k]*W[n,k] (+bias[n]) (+add[m,n])
// 128x128x16 tile, 256 threads, 8x8/thread split fragments, double buffer.
// ---------------------------------------------------------------------------
template <bool HAS_BIAS, bool HAS_ADD>
__global__ void __launch_bounds__(256, 2)
gemm_nt_v2(const float* __restrict__ A, const float* __restrict__ W,
           const float* __restrict__ bias, const float* __restrict__ add,
           float* __restrict__ C, int M, int N, int K)
{
    __shared__ float As[2][16][132];
    __shared__ float Bs[2][16][132];

    const int tid = threadIdx.x;
    const int tx  = tid & 15;
    const int ty  = tid >> 4;
    const int m0  = blockIdx.y * 128;
    const int n0  = blockIdx.x * 128;

    const int lrow = tid >> 2;         // 0..63
    const int lk4  = (tid & 3) * 4;    // 0,4,8,12

    const float* Ag = A + (size_t)(m0 + lrow) * K + lk4;
    const float* Wg = W + (size_t)(n0 + lrow) * K + lk4;
    const size_t rstep = (size_t)64 * K;

    float4 pa0 = *(const float4*)(Ag);
    float4 pa1 = *(const float4*)(Ag + rstep);
    float4 pb0 = *(const float4*)(Wg);
    float4 pb1 = *(const float4*)(Wg + rstep);

    float acc[8][8] = {};
    const int nk = K / 16;
    int buf = 0;

    As[0][lk4+0][lrow]    = pa0.x; As[0][lk4+1][lrow]    = pa0.y;
    As[0][lk4+2][lrow]    = pa0.z; As[0][lk4+3][lrow]    = pa0.w;
    As[0][lk4+0][lrow+64] = pa1.x; As[0][lk4+1][lrow+64] = pa1.y;
    As[0][lk4+2][lrow+64] = pa1.z; As[0][lk4+3][lrow+64] = pa1.w;
    Bs[0][lk4+0][lrow]    = pb0.x; Bs[0][lk4+1][lrow]    = pb0.y;
    Bs[0][lk4+2][lrow]    = pb0.z; Bs[0][lk4+3][lrow]    = pb0.w;
    Bs[0][lk4+0][lrow+64] = pb1.x; Bs[0][lk4+1][lrow+64] = pb1.y;
    Bs[0][lk4+2][lrow+64] = pb1.z; Bs[0][lk4+3][lrow+64] = pb1.w;
    __syncthreads();

    for (int kt = 0; kt < nk; kt++) {
        const bool more = (kt + 1 < nk);
        if (more) {
            const int off = (kt + 1) * 16;
            pa0 = *(const float4*)(Ag + off);
            pa1 = *(const float4*)(Ag + rstep + off);
            pb0 = *(const float4*)(Wg + off);
            pb1 = *(const float4*)(Wg + rstep + off);
        }

        #pragma unroll
        for (int kk = 0; kk < 16; kk++) {
            float4 x0 = *(const float4*)&As[buf][kk][ty * 4];
            float4 x1 = *(const float4*)&As[buf][kk][64 + ty * 4];
            float4 y0 = *(const float4*)&Bs[buf][kk][tx * 4];
            float4 y1 = *(const float4*)&Bs[buf][kk][64 + tx * 4];
            float xa[8] = {x0.x, x0.y, x0.z, x0.w, x1.x, x1.y, x1.z, x1.w};
            float yb[8] = {y0.x, y0.y, y0.z, y0.w, y1.x, y1.y, y1.z, y1.w};
            #pragma unroll
            for (int i = 0; i < 8; i++)
                #pragma unroll
                for (int j = 0; j < 8; j++)
                    acc[i][j] += xa[i] * yb[j];
        }

        if (more) {
            buf ^= 1;
            __syncthreads();
            As[buf][lk4+0][lrow]    = pa0.x; As[buf][lk4+1][lrow]    = pa0.y;
            As[buf][lk4+2][lrow]    = pa0.z; As[buf][lk4+3][lrow]    = pa0.w;
            As[buf][lk4+0][lrow+64] = pa1.x; As[buf][lk4+1][lrow+64] = pa1.y;
            As[buf][lk4+2][lrow+64] = pa1.z; As[buf][lk4+3][lrow+64] = pa1.w;
            Bs[buf][lk4+0][lrow]    = pb0.x; Bs[buf][lk4+1][lrow]    = pb0.y;
            Bs[buf][lk4+2][lrow]    = pb0.z; Bs[buf][lk4+3][lrow]    = pb0.w;
            Bs[buf][lk4+0][lrow+64] = pb1.x; Bs[buf][lk4+1][lrow+64] = pb1.y;
            Bs[buf][lk4+2][lrow+64] = pb1.z; Bs[buf][lk4+3][lrow+64] = pb1.w;
            __syncthreads();
        }
    }

    float4 bv0 = make_float4(0.f,0.f,0.f,0.f), bv1 = bv0;
    if (HAS_BIAS) {
        bv0 = *(const float4*)&bias[n0 + tx * 4];
        bv1 = *(const float4*)&bias[n0 + 64 + tx * 4];
    }

    #pragma unroll
    for (int ih = 0; ih < 2; ih++) {
        #pragma unroll
        for (int ii = 0; ii < 4; ii++) {
            const int row = m0 + ih * 64 + ty * 4 + ii;
            #pragma unroll
            for (int jh = 0; jh < 2; jh++) {
                const int col = n0 + jh * 64 + tx * 4;
                const float4 bb = jh ? bv1 : bv0;
                float4 o;
                o.x = acc[ih*4+ii][jh*4+0] + bb.x;
                o.y = acc[ih*4+ii][jh*4+1] + bb.y;
                o.z = acc[ih*4+ii][jh*4+2] + bb.z;
                o.w = acc[ih*4+ii][jh*4+3] + bb.w;
                if (HAS_ADD) {
                    float4 xv = *(const float4*)&add[(size_t)row * N + col];
                    o.x += xv.x; o.y += xv.y; o.z += xv.z; o.w += xv.w;
                }
                *(float4*)&C[(size_t)row * N + col] = o;
            }
        }
    }
}

// ---------------------------------------------------------------------------
// RMSNorm + RoPE (in-place). One warp per (b*s, h) row.
// ---------------------------------------------------------------------------
__global__ void __launch_bounds__(256)
norm_rope_kernel(float* __restrict__ buf, const float* __restrict__ norm_w)
{
    int gwarp = (blockIdx.x * blockDim.x + threadIdx.x) >> 5;
    int lane  = threadIdx.x & 31;
    if (gwarp >= M_TOTAL * N_HEAD) return;

    int m = gwarp >> 4;
    int h = gwarp & 15;
    int s = m & (N_CTX - 1);

    float* p = buf + (size_t)m * D_MODEL + h * D_HEAD;
    float2 x = *(float2*)(p + 2 * lane);

    float ss = x.x * x.x + x.y * x.y;
    #pragma unroll
    for (int off = 16; off > 0; off >>= 1)
        ss += __shfl_xor_sync(0xFFFFFFFFu, ss, off);

    float r = rsqrtf(ss * (1.0f / 64.0f) + 1.1920929e-07f);

    int d0 = 2 * lane, d1 = 2 * lane + 1;
    float xn0 = x.x * r * norm_w[d0];
    float xn1 = x.y * r * norm_w[d1];

    int j0 = d0 & 31, j1 = d1 & 31;
    float c0 = g_cos[s * 32 + j0], s0 = g_sin[s * 32 + j0];
    float c1 = g_cos[s * 32 + j1], s1 = g_sin[s * 32 + j1];

    float o0 = xn0 * c0 - xn1 * s0;
    float o1 = xn1 * c1 + xn0 * s1;
    *(float2*)(p + 2 * lane) = make_float2(o0, o1);
}

// ---------------------------------------------------------------------------
// Fused quadratic attention v2: z[q,:] = sum_{k<=q} (q.k/64)^2 * v[k,:]
// CTA = 128 q-rows x one (b,h); k-tiles of 64. 256 threads, 8x4 fragments.
// Dynamic smem: Qs[64][132] Ks[64][68] Vs[64][68] Ssq[64][136] = 101 KB.
// ---------------------------------------------------------------------------
#define ATTN_SMEM_FLOATS (64*132 + 64*68 + 64*68 + 64*136)

__global__ void __launch_bounds__(256, 2)
attn_v2()
{
    extern __shared__ float sm[];
    float* Qs  = sm;                 // [64][132] (d-major, q cols 0..127)
    float* Ks  = Qs + 64 * 132;      // [64][68]  (d-major, k cols 0..63)
    float* Vs  = Ks + 64 * 68;       // [64][68]  (k-major, d cols)
    float* Ssq = Vs + 64 * 68;       // [64][136] (k-major, q cols)

    const int tid = threadIdx.x;
    const int tx  = tid & 15;
    const int ty  = tid >> 4;
    const int qi  = (N_CTX / 128 - 1) - (int)blockIdx.x;  // heavy first
    const int bh  = blockIdx.y;
    const int b   = bh >> 4;
    const int h   = bh & 15;
    const int q0  = qi * 128;

    const float* Qg = g_q + (size_t)b * N_CTX * D_MODEL + h * D_HEAD;
    const float* Kg = g_k + (size_t)b * N_CTX * D_MODEL + h * D_HEAD;
    const float* Vg = g_v + (size_t)b * N_CTX * D_MODEL + h * D_HEAD;

    // Q tile (128x64) transposed into Qs[d][q]
    #pragma unroll
    for (int it = 0; it < 8; it++) {
        int f4  = it * 256 + tid;       // 0..2047
        int row = f4 >> 4;              // 0..127
        int d4  = (f4 & 15) * 4;
        float4 v = *(const float4*)&Qg[(size_t)(q0 + row) * D_MODEL + d4];
        Qs[(d4+0)*132 + row] = v.x; Qs[(d4+1)*132 + row] = v.y;
        Qs[(d4+2)*132 + row] = v.z; Qs[(d4+3)*132 + row] = v.w;
    }

    float zacc[8][4] = {};
    const int nkt = 2 * qi + 2;

    for (int kt = 0; kt < nkt; kt++) {
        __syncthreads();   // protects Ks/Vs/Ssq reuse; covers Qs stores at kt=0
        const int k0 = kt * 64;

        // K,V tiles (64x64)
        #pragma unroll
        for (int it = 0; it < 4; it++) {
            int f4  = it * 256 + tid;   // 0..1023
            int row = f4 >> 4;          // 0..63
            int d4  = (f4 & 15) * 4;
            float4 kv = *(const float4*)&Kg[(size_t)(k0 + row) * D_MODEL + d4];
            Ks[(d4+0)*68 + row] = kv.x; Ks[(d4+1)*68 + row] = kv.y;
            Ks[(d4+2)*68 + row] = kv.z; Ks[(d4+3)*68 + row] = kv.w;
            float4 vv = *(const float4*)&Vg[(size_t)(k0 + row) * D_MODEL + d4];
            *(float4*)&Vs[row * 68 + d4] = vv;
        }
        __syncthreads();

        // S fragments: 8 q-rows (split) x 4 k-cols
        float sacc[8][4] = {};
        #pragma unroll 8
        for (int d = 0; d < 64; d++) {
            float4 xq0 = *(const float4*)&Qs[d * 132 + ty * 4];
            float4 xq1 = *(const float4*)&Qs[d * 132 + 64 + ty * 4];
            float4 kb  = *(const float4*)&Ks[d * 68 + tx * 4];
            float qa[8] = {xq0.x, xq0.y, xq0.z, xq0.w,
                           xq1.x, xq1.y, xq1.z, xq1.w};
            #pragma unroll
            for (int i = 0; i < 8; i++) {
                sacc[i][0] += qa[i] * kb.x;
                sacc[i][1] += qa[i] * kb.y;
                sacc[i][2] += qa[i] * kb.z;
                sacc[i][3] += qa[i] * kb.w;
            }
        }

        // pattern = (S/64)^2 (+ causal on last two tiles); store transposed
        // Ssq[k][q], j rotated per-lane, float4 over q (4-phase optimal).
        const bool diag = (kt >= 2 * qi);
        #pragma unroll
        for (int jj = 0; jj < 4; jj++) {
            const int j    = (jj + tx) & 3;
            const int kloc = tx * 4 + j;
            const int kg   = k0 + kloc;
            #pragma unroll
            for (int qh = 0; qh < 2; qh++) {
                float4 pv;
                float* pp = &pv.x;
                #pragma unroll
                for (int ii = 0; ii < 4; ii++) {
                    float p = sacc[qh*4+ii][j] * 0.015625f;
                    p *= p;
                    if (diag && kg > q0 + qh * 64 + ty * 4 + ii) p = 0.0f;
                    pp[ii] = p;
                }
                *(float4*)&Ssq[kloc * 136 + qh * 64 + ty * 4] = pv;
            }
        }
        __syncthreads();

        // Z += P . V
        #pragma unroll 8
        for (int kk = 0; kk < 64; kk++) {
            float4 s0 = *(const float4*)&Ssq[kk * 136 + ty * 4];
            float4 s1 = *(const float4*)&Ssq[kk * 136 + 64 + ty * 4];
            float4 vb = *(const float4*)&Vs[kk * 68 + tx * 4];
            float sa[8] = {s0.x, s0.y, s0.z, s0.w, s1.x, s1.y, s1.z, s1.w};
            #pragma unroll
            for (int r = 0; r < 8; r++) {
                zacc[r][0] += sa[r] * vb.x;
                zacc[r][1] += sa[r] * vb.y;
                zacc[r][2] += sa[r] * vb.z;
                zacc[r][3] += sa[r] * vb.w;
            }
        }
    }

    float* Zg = g_z + (size_t)b * N_CTX * D_MODEL + h * D_HEAD;
    #pragma unroll
    for (int qh = 0; qh < 2; qh++) {
        #pragma unroll
        for (int ii = 0; ii < 4; ii++) {
            const int row = q0 + qh * 64 + ty * 4 + ii;
            float4 o = make_float4(zacc[qh*4+ii][0], zacc[qh*4+ii][1],
                                   zacc[qh*4+ii][2], zacc[qh*4+ii][3]);
            *(float4*)&Zg[(size_t)row * D_MODEL + tx * 4] = o;
        }
    }
}

// ---------------------------------------------------------------------------
// Launch
// ---------------------------------------------------------------------------
extern "C" void kernel_launch(void* const* d_in, const int* in_sizes, int n_in,
                              void* d_out, int out_size)
{
    const float* x      = (const float*)d_in[0];
    const float* Wq     = (const float*)d_in[1];
    const float* bq     = (const float*)d_in[2];
    const float* Wk     = (const float*)d_in[3];
    const float* bk     = (const float*)d_in[4];
    const float* Wv     = (const float*)d_in[5];
    const float* bv     = (const float*)d_in[6];
    const float* Wo     = (const float*)d_in[7];
    const float* norm_w = (const float*)d_in[8];
    float* out          = (float*)d_out;

    float *q, *k, *v, *z;
    cudaGetSymbolAddress((void**)&q, g_q);
    cudaGetSymbolAddress((void**)&k, g_k);
    cudaGetSymbolAddress((void**)&v, g_v);
    cudaGetSymbolAddress((void**)&z, g_z);

    cudaFuncSetAttribute(attn_v2, cudaFuncAttributeMaxDynamicSharedMemorySize,
                         ATTN_SMEM_FLOATS * 4);

    dim3 gdim(D_MODEL / 128, M_TOTAL / 128);  // (8, 32)
    dim3 bdim(256);

    rope_table_kernel<<<N_CTX, 32>>>();

    gemm_nt_v2<true, false><<<gdim, bdim>>>(x, Wq, bq, nullptr, q,
                                            M_TOTAL, D_MODEL, D_MODEL);
    gemm_nt_v2<true, false><<<gdim, bdim>>>(x, Wk, bk, nullptr, k,
                                            M_TOTAL, D_MODEL, D_MODEL);
    gemm_nt_v2<true, false><<<gdim, bdim>>>(x, Wv, bv, nullptr, v,
                                            M_TOTAL, D_MODEL, D_MODEL);

    int nblocks = (M_TOTAL * N_HEAD) / 8;     // 8 warps per 256-thread block
    norm_rope_kernel<<<nblocks, 256>>>(q, norm_w);
    norm_rope_kernel<<<nblocks, 256>>>(k, norm_w);

    attn_v2<<<dim3(N_CTX / 128, BATCH * N_HEAD), 256,
              ATTN_SMEM_FLOATS * 4>>>();

    gemm_nt_v2<false, true><<<gdim, bdim>>>(z, Wo, nullptr, x, out,
                                            M_TOTAL, D_MODEL, D_MODEL);
}

// round 13
// speedup vs baseline: 2.7190x; 1.3747x over previous
#include <cuda_runtime.h>
#include <cuda_bf16.h>
#include <math.h>
#include <stdint.h>

#define D_MODEL 1024
#define N_HEAD  16
#define D_HEAD  64
#define N_CTX   2048
#define BATCH   2
#define M_TOTAL (BATCH * N_CTX)   /* 4096 rows */

// fp32 scratch
__device__ float g_q[(size_t)M_TOTAL * D_MODEL];
__device__ float g_k[(size_t)M_TOTAL * D_MODEL];
__device__ float g_v[(size_t)M_TOTAL * D_MODEL];
__device__ float g_z[(size_t)M_TOTAL * D_MODEL];
__device__ float g_cos[N_CTX * 32];
__device__ float g_sin[N_CTX * 32];

// bf16 split scratch
__device__ __nv_bfloat16 g_xh[(size_t)M_TOTAL * D_MODEL];
__device__ __nv_bfloat16 g_xl[(size_t)M_TOTAL * D_MODEL];
__device__ __nv_bfloat16 g_zh[(size_t)M_TOTAL * D_MODEL];
__device__ __nv_bfloat16 g_zl[(size_t)M_TOTAL * D_MODEL];
__device__ __nv_bfloat16 g_wqh[(size_t)D_MODEL * D_MODEL];
__device__ __nv_bfloat16 g_wql[(size_t)D_MODEL * D_MODEL];
__device__ __nv_bfloat16 g_wkh[(size_t)D_MODEL * D_MODEL];
__device__ __nv_bfloat16 g_wkl[(size_t)D_MODEL * D_MODEL];
__device__ __nv_bfloat16 g_wvh[(size_t)D_MODEL * D_MODEL];
__device__ __nv_bfloat16 g_wvl[(size_t)D_MODEL * D_MODEL];
__device__ __nv_bfloat16 g_woh[(size_t)D_MODEL * D_MODEL];
__device__ __nv_bfloat16 g_wol[(size_t)D_MODEL * D_MODEL];

// ---------------------------------------------------------------------------
// RoPE table: fp64 trig of the fp32-rounded angle (fast-math-proof).
// ---------------------------------------------------------------------------
__global__ void rope_table_kernel()
{
    int j = threadIdx.x;
    int s = blockIdx.x;
    float inv_freq = (float)pow(10000.0, -(double)j / 32.0);
    float a = (float)s * inv_freq;
    double sd, cd;
    sincos((double)a, &sd, &cd);
    g_cos[s * 32 + j] = (float)cd;
    g_sin[s * 32 + j] = (float)sd;
}

// ---------------------------------------------------------------------------
// fp32 -> (bf16 hi, bf16 lo) split.  n4 = element count / 4.
// ---------------------------------------------------------------------------
__global__ void __launch_bounds__(256)
split_kernel(const float* __restrict__ s, __nv_bfloat16* __restrict__ hi,
             __nv_bfloat16* __restrict__ lo, int n4)
{
    int i = blockIdx.x * 256 + threadIdx.x;
    if (i >= n4) return;
    float4 xv = ((const float4*)s)[i];
    float xs[4] = {xv.x, xv.y, xv.z, xv.w};
    __nv_bfloat16 h[4], l[4];
    #pragma unroll
    for (int j = 0; j < 4; j++) {
        h[j] = __float2bfloat16_rn(xs[j]);
        l[j] = __float2bfloat16_rn(xs[j] - __bfloat162float(h[j]));
    }
    ((__nv_bfloat162*)hi)[2*i+0] = __nv_bfloat162(h[0], h[1]);
    ((__nv_bfloat162*)hi)[2*i+1] = __nv_bfloat162(h[2], h[3]);
    ((__nv_bfloat162*)lo)[2*i+0] = __nv_bfloat162(l[0], l[1]);
    ((__nv_bfloat162*)lo)[2*i+1] = __nv_bfloat162(l[2], l[3]);
}

// ---------------------------------------------------------------------------
// Tensor-core NT GEMM via mma.sync (HMMA, valid on base sm_103 PTX target):
//   C[m,n] = sum_k A[m,k]*B[n,k] (+bias[n]) (+add[m,n]),  bf16x3 split.
// CTA 128x128, 8 warps (2x4), warp tile 64x32, K-chunks of 32, cp.async
// double buffer. Smem tile stride 40 bf16 -> conflict-free fragment LDS.
// ---------------------------------------------------------------------------
#define KC        32
#define TSTRIDE   40                       /* bf16 elems per smem row */
#define TILE_ELS  (128 * TSTRIDE)          /* 5120 elems = 10240 B */
#define BUF_ELS   (4 * TILE_ELS)           /* Ah, Al, Wh, Wl */
#define GEMM_SMEM (2 * BUF_ELS * 2)        /* bytes: 81920 */

__device__ __forceinline__ uint32_t smem_u32(const void* p) {
    uint32_t a;
    asm("{ .reg .u64 t; cvta.to.shared.u64 t, %1; cvt.u32.u64 %0, t; }"
        : "=r"(a) : "l"(p));
    return a;
}

__device__ __forceinline__ void mma_bf16(float* c, uint32_t a0, uint32_t a1,
                                         uint32_t a2, uint32_t a3,
                                         uint32_t b0, uint32_t b1) {
    asm volatile(
        "mma.sync.aligned.m16n8k16.row.col.f32.bf16.bf16.f32 "
        "{%0,%1,%2,%3}, {%4,%5,%6,%7}, {%8,%9}, {%0,%1,%2,%3};"
        : "+f"(c[0]), "+f"(c[1]), "+f"(c[2]), "+f"(c[3])
        : "r"(a0), "r"(a1), "r"(a2), "r"(a3), "r"(b0), "r"(b1));
}

template <bool HAS_BIAS, bool HAS_ADD>
__global__ void __launch_bounds__(256)
gemm_tc(const __nv_bfloat16* __restrict__ Ah, const __nv_bfloat16* __restrict__ Al,
        const __nv_bfloat16* __restrict__ Bh, const __nv_bfloat16* __restrict__ Bl,
        const float* __restrict__ bias, const float* __restrict__ add,
        float* __restrict__ C)
{
    extern __shared__ __nv_bfloat16 sm[];
    const int tid = threadIdx.x;
    const int wid = tid >> 5;
    const int lane = tid & 31;
    const int g   = lane >> 2;         // group id 0..7
    const int tig = lane & 3;          // thread in group
    const int wm  = (wid & 1) * 64;    // warp m offset in tile
    const int wn  = (wid >> 1) * 32;   // warp n offset in tile
    const int n0  = blockIdx.x * 128;
    const int m0  = blockIdx.y * 128;
    const int K   = D_MODEL;

    // async load of one 128x32 bf16 tile into smem (2 iters x 256 thr x 16B)
    #define ISSUE_TILE(SRC, RB, BASE, CH) do {                                 \
        _Pragma("unroll")                                                      \
        for (int it = 0; it < 2; it++) {                                       \
            int idx  = it * 256 + tid;      /* 0..511 */                       \
            int row  = idx >> 2;            /* 0..127 */                       \
            int col8 = (idx & 3) * 8;                                         \
            uint32_t daddr = smem_u32(&sm[(BASE) + row * TSTRIDE + col8]);     \
            const __nv_bfloat16* src = (SRC) + (size_t)((RB) + row) * K        \
                                       + (CH) * KC + col8;                     \
            asm volatile("cp.async.cg.shared.global [%0], [%1], 16;"           \
                         :: "r"(daddr), "l"(src));                             \
        }                                                                      \
    } while (0)

    #define ISSUE_CHUNK(CH, BUF) do {                                         \
        const int bb = (BUF) * BUF_ELS;                                       \
        ISSUE_TILE(Ah, m0, bb + 0 * TILE_ELS, CH);                            \
        ISSUE_TILE(Al, m0, bb + 1 * TILE_ELS, CH);                            \
        ISSUE_TILE(Bh, n0, bb + 2 * TILE_ELS, CH);                            \
        ISSUE_TILE(Bl, n0, bb + 3 * TILE_ELS, CH);                            \
        asm volatile("cp.async.commit_group;" ::: "memory");                  \
    } while (0)

    float acc[4][4][4] = {};   // [fm][fn][frag]

    ISSUE_CHUNK(0, 0);

    const int NCH = K / KC;    // 32
    for (int c = 0; c < NCH; c++) {
        const int buf = c & 1;
        if (c + 1 < NCH) {
            ISSUE_CHUNK(c + 1, buf ^ 1);
            asm volatile("cp.async.wait_group 1;" ::: "memory");
        } else {
            asm volatile("cp.async.wait_group 0;" ::: "memory");
        }
        __syncthreads();

        const int bb  = buf * BUF_ELS;
        const int Ahb = bb,               Alb = bb + TILE_ELS;
        const int Whb = bb + 2 * TILE_ELS, Wlb = bb + 3 * TILE_ELS;

        #pragma unroll
        for (int ks = 0; ks < KC; ks += 16) {
            // B fragments (hi & lo) for 4 n-frags
            uint32_t bh[4][2], bl[4][2];
            #pragma unroll
            for (int fn = 0; fn < 4; fn++) {
                int rn = (wn + fn * 8 + g) * TSTRIDE + ks + tig * 2;
                bh[fn][0] = *(const uint32_t*)&sm[Whb + rn];
                bh[fn][1] = *(const uint32_t*)&sm[Whb + rn + 8];
                bl[fn][0] = *(const uint32_t*)&sm[Wlb + rn];
                bl[fn][1] = *(const uint32_t*)&sm[Wlb + rn + 8];
            }
            #pragma unroll
            for (int fm = 0; fm < 4; fm++) {
                int r0 = (wm + fm * 16 + g) * TSTRIDE + ks + tig * 2;
                int r8 = r0 + 8 * TSTRIDE;
                uint32_t ah0 = *(const uint32_t*)&sm[Ahb + r0];
                uint32_t ah1 = *(const uint32_t*)&sm[Ahb + r8];
                uint32_t ah2 = *(const uint32_t*)&sm[Ahb + r0 + 8];
                uint32_t ah3 = *(const uint32_t*)&sm[Ahb + r8 + 8];
                uint32_t al0 = *(const uint32_t*)&sm[Alb + r0];
                uint32_t al1 = *(const uint32_t*)&sm[Alb + r8];
                uint32_t al2 = *(const uint32_t*)&sm[Alb + r0 + 8];
                uint32_t al3 = *(const uint32_t*)&sm[Alb + r8 + 8];
                #pragma unroll
                for (int fn = 0; fn < 4; fn++) {
                    mma_bf16(acc[fm][fn], ah0, ah1, ah2, ah3,
                             bh[fn][0], bh[fn][1]);
                    mma_bf16(acc[fm][fn], ah0, ah1, ah2, ah3,
                             bl[fn][0], bl[fn][1]);
                    mma_bf16(acc[fm][fn], al0, al1, al2, al3,
                             bh[fn][0], bh[fn][1]);
                }
            }
        }
        __syncthreads();
    }
    #undef ISSUE_CHUNK
    #undef ISSUE_TILE

    // Epilogue: c0,c1 -> (row g, col 2*tig), c2,c3 -> (row g+8, col 2*tig)
    #pragma unroll
    for (int fm = 0; fm < 4; fm++) {
        #pragma unroll
        for (int fn = 0; fn < 4; fn++) {
            const int col = n0 + wn + fn * 8 + tig * 2;
            float bx = 0.f, by = 0.f;
            if (HAS_BIAS) { bx = bias[col]; by = bias[col + 1]; }
            #pragma unroll
            for (int hrow = 0; hrow < 2; hrow++) {
                const int row = m0 + wm + fm * 16 + g + hrow * 8;
                float ox = acc[fm][fn][hrow * 2 + 0] + bx;
                float oy = acc[fm][fn][hrow * 2 + 1] + by;
                if (HAS_ADD) {
                    float2 av = *(const float2*)&add[(size_t)row * D_MODEL + col];
                    ox += av.x; oy += av.y;
                }
                *(float2*)&C[(size_t)row * D_MODEL + col] = make_float2(ox, oy);
            }
        }
    }
}

// ---------------------------------------------------------------------------
// RMSNorm + RoPE (in-place). One warp per (b*s, h) row.
// ---------------------------------------------------------------------------
__global__ void __launch_bounds__(256)
norm_rope_kernel(float* __restrict__ buf, const float* __restrict__ norm_w)
{
    int gwarp = (blockIdx.x * blockDim.x + threadIdx.x) >> 5;
    int lane  = threadIdx.x & 31;
    if (gwarp >= M_TOTAL * N_HEAD) return;

    int m = gwarp >> 4;
    int h = gwarp & 15;
    int s = m & (N_CTX - 1);

    float* p = buf + (size_t)m * D_MODEL + h * D_HEAD;
    float2 x = *(float2*)(p + 2 * lane);

    float ss = x.x * x.x + x.y * x.y;
    #pragma unroll
    for (int off = 16; off > 0; off >>= 1)
        ss += __shfl_xor_sync(0xFFFFFFFFu, ss, off);

    float r = rsqrtf(ss * (1.0f / 64.0f) + 1.1920929e-07f);

    int d0 = 2 * lane, d1 = 2 * lane + 1;
    float xn0 = x.x * r * norm_w[d0];
    float xn1 = x.y * r * norm_w[d1];

    int j0 = d0 & 31, j1 = d1 & 31;
    float c0 = g_cos[s * 32 + j0], s0 = g_sin[s * 32 + j0];
    float c1 = g_cos[s * 32 + j1], s1 = g_sin[s * 32 + j1];

    float o0 = xn0 * c0 - xn1 * s0;
    float o1 = xn1 * c1 + xn0 * s1;
    *(float2*)(p + 2 * lane) = make_float2(o0, o1);
}

// ---------------------------------------------------------------------------
// Fused quadratic attention v2 (SIMT fp32, unchanged R8 winner).
// ---------------------------------------------------------------------------
#define ATTN_SMEM_FLOATS (64*132 + 64*68 + 64*68 + 64*136)

__global__ void __launch_bounds__(256, 2)
attn_v2()
{
    extern __shared__ float smf[];
    float* Qs  = smf;                // [64][132]
    float* Ks  = Qs + 64 * 132;      // [64][68]
    float* Vs  = Ks + 64 * 68;       // [64][68]
    float* Ssq = Vs + 64 * 68;       // [64][136]

    const int tid = threadIdx.x;
    const int tx  = tid & 15;
    const int ty  = tid >> 4;
    const int qi  = (N_CTX / 128 - 1) - (int)blockIdx.x;
    const int bh  = blockIdx.y;
    const int b   = bh >> 4;
    const int h   = bh & 15;
    const int q0  = qi * 128;

    const float* Qg = g_q + (size_t)b * N_CTX * D_MODEL + h * D_HEAD;
    const float* Kg = g_k + (size_t)b * N_CTX * D_MODEL + h * D_HEAD;
    const float* Vg = g_v + (size_t)b * N_CTX * D_MODEL + h * D_HEAD;

    #pragma unroll
    for (int it = 0; it < 8; it++) {
        int f4  = it * 256 + tid;
        int row = f4 >> 4;
        int d4  = (f4 & 15) * 4;
        float4 v = *(const float4*)&Qg[(size_t)(q0 + row) * D_MODEL + d4];
        Qs[(d4+0)*132 + row] = v.x; Qs[(d4+1)*132 + row] = v.y;
        Qs[(d4+2)*132 + row] = v.z; Qs[(d4+3)*132 + row] = v.w;
    }

    float zacc[8][4] = {};
    const int nkt = 2 * qi + 2;

    for (int kt = 0; kt < nkt; kt++) {
        __syncthreads();
        const int k0 = kt * 64;

        #pragma unroll
        for (int it = 0; it < 4; it++) {
            int f4  = it * 256 + tid;
            int row = f4 >> 4;
            int d4  = (f4 & 15) * 4;
            float4 kv = *(const float4*)&Kg[(size_t)(k0 + row) * D_MODEL + d4];
            Ks[(d4+0)*68 + row] = kv.x; Ks[(d4+1)*68 + row] = kv.y;
            Ks[(d4+2)*68 + row] = kv.z; Ks[(d4+3)*68 + row] = kv.w;
            float4 vv = *(const float4*)&Vg[(size_t)(k0 + row) * D_MODEL + d4];
            *(float4*)&Vs[row * 68 + d4] = vv;
        }
        __syncthreads();

        float sacc[8][4] = {};
        #pragma unroll 8
        for (int d = 0; d < 64; d++) {
            float4 xq0 = *(const float4*)&Qs[d * 132 + ty * 4];
            float4 xq1 = *(const float4*)&Qs[d * 132 + 64 + ty * 4];
            float4 kb  = *(const float4*)&Ks[d * 68 + tx * 4];
            float qa[8] = {xq0.x, xq0.y, xq0.z, xq0.w,
                           xq1.x, xq1.y, xq1.z, xq1.w};
            #pragma unroll
            for (int i = 0; i < 8; i++) {
                sacc[i][0] += qa[i] * kb.x;
                sacc[i][1] += qa[i] * kb.y;
                sacc[i][2] += qa[i] * kb.z;
                sacc[i][3] += qa[i] * kb.w;
            }
        }

        const bool diag = (kt >= 2 * qi);
        #pragma unroll
        for (int jj = 0; jj < 4; jj++) {
            const int j    = (jj + tx) & 3;
            const int kloc = tx * 4 + j;
            const int kg   = k0 + kloc;
            #pragma unroll
            for (int qh = 0; qh < 2; qh++) {
                float4 pv;
                float* pp = &pv.x;
                #pragma unroll
                for (int ii = 0; ii < 4; ii++) {
                    float p = sacc[qh*4+ii][j] * 0.015625f;
                    p *= p;
                    if (diag && kg > q0 + qh * 64 + ty * 4 + ii) p = 0.0f;
                    pp[ii] = p;
                }
                *(float4*)&Ssq[kloc * 136 + qh * 64 + ty * 4] = pv;
            }
        }
        __syncthreads();

        #pragma unroll 8
        for (int kk = 0; kk < 64; kk++) {
            float4 s0 = *(const float4*)&Ssq[kk * 136 + ty * 4];
            float4 s1 = *(const float4*)&Ssq[kk * 136 + 64 + ty * 4];
            float4 vb = *(const float4*)&Vs[kk * 68 + tx * 4];
            float sa[8] = {s0.x, s0.y, s0.z, s0.w, s1.x, s1.y, s1.z, s1.w};
            #pragma unroll
            for (int r = 0; r < 8; r++) {
                zacc[r][0] += sa[r] * vb.x;
                zacc[r][1] += sa[r] * vb.y;
                zacc[r][2] += sa[r] * vb.z;
                zacc[r][3] += sa[r] * vb.w;
            }
        }
    }

    float* Zg = g_z + (size_t)b * N_CTX * D_MODEL + h * D_HEAD;
    #pragma unroll
    for (int qh = 0; qh < 2; qh++) {
        #pragma unroll
        for (int ii = 0; ii < 4; ii++) {
            const int row = q0 + qh * 64 + ty * 4 + ii;
            float4 o = make_float4(zacc[qh*4+ii][0], zacc[qh*4+ii][1],
                                   zacc[qh*4+ii][2], zacc[qh*4+ii][3]);
            *(float4*)&Zg[(size_t)row * D_MODEL + tx * 4] = o;
        }
    }
}

// ---------------------------------------------------------------------------
// Launch
// ---------------------------------------------------------------------------
extern "C" void kernel_launch(void* const* d_in, const int* in_sizes, int n_in,
                              void* d_out, int out_size)
{
    const float* x      = (const float*)d_in[0];
    const float* Wq     = (const float*)d_in[1];
    const float* bq     = (const float*)d_in[2];
    const float* Wk     = (const float*)d_in[3];
    const float* bk     = (const float*)d_in[4];
    const float* Wv     = (const float*)d_in[5];
    const float* bv     = (const float*)d_in[6];
    const float* Wo     = (const float*)d_in[7];
    const float* norm_w = (const float*)d_in[8];
    float* out          = (float*)d_out;

    float *q, *k, *v, *z;
    cudaGetSymbolAddress((void**)&q, g_q);
    cudaGetSymbolAddress((void**)&k, g_k);
    cudaGetSymbolAddress((void**)&v, g_v);
    cudaGetSymbolAddress((void**)&z, g_z);

    __nv_bfloat16 *xh, *xl, *zh, *zl;
    __nv_bfloat16 *wqh, *wql, *wkh, *wkl, *wvh, *wvl, *woh, *wol;
    cudaGetSymbolAddress((void**)&xh,  g_xh);  cudaGetSymbolAddress((void**)&xl,  g_xl);
    cudaGetSymbolAddress((void**)&zh,  g_zh);  cudaGetSymbolAddress((void**)&zl,  g_zl);
    cudaGetSymbolAddress((void**)&wqh, g_wqh); cudaGetSymbolAddress((void**)&wql, g_wql);
    cudaGetSymbolAddress((void**)&wkh, g_wkh); cudaGetSymbolAddress((void**)&wkl, g_wkl);
    cudaGetSymbolAddress((void**)&wvh, g_wvh); cudaGetSymbolAddress((void**)&wvl, g_wvl);
    cudaGetSymbolAddress((void**)&woh, g_woh); cudaGetSymbolAddress((void**)&wol, g_wol);

    cudaFuncSetAttribute(attn_v2, cudaFuncAttributeMaxDynamicSharedMemorySize,
                         ATTN_SMEM_FLOATS * 4);
    cudaFuncSetAttribute(gemm_tc<true, false>,
                         cudaFuncAttributeMaxDynamicSharedMemorySize, GEMM_SMEM);
    cudaFuncSetAttribute(gemm_tc<false, true>,
                         cudaFuncAttributeMaxDynamicSharedMemorySize, GEMM_SMEM);

    rope_table_kernel<<<N_CTX, 32>>>();

    // fp32 -> bf16 hi/lo splits
    const int n4x = (M_TOTAL * D_MODEL) / 4;
    const int n4w = (D_MODEL * D_MODEL) / 4;
    split_kernel<<<n4x / 256, 256>>>(x,  xh,  xl,  n4x);
    split_kernel<<<n4w / 256, 256>>>(Wq, wqh, wql, n4w);
    split_kernel<<<n4w / 256, 256>>>(Wk, wkh, wkl, n4w);
    split_kernel<<<n4w / 256, 256>>>(Wv, wvh, wvl, n4w);
    split_kernel<<<n4w / 256, 256>>>(Wo, woh, wol, n4w);

    dim3 ggrid(D_MODEL / 128, M_TOTAL / 128);    // (8, 32)
    gemm_tc<true, false><<<ggrid, 256, GEMM_SMEM>>>(xh, xl, wqh, wql, bq, nullptr, q);
    gemm_tc<true, false><<<ggrid, 256, GEMM_SMEM>>>(xh, xl, wkh, wkl, bk, nullptr, k);
    gemm_tc<true, false><<<ggrid, 256, GEMM_SMEM>>>(xh, xl, wvh, wvl, bv, nullptr, v);

    int nblocks = (M_TOTAL * N_HEAD) / 8;
    norm_rope_kernel<<<nblocks, 256>>>(q, norm_w);
    norm_rope_kernel<<<nblocks, 256>>>(k, norm_w);

    attn_v2<<<dim3(N_CTX / 128, BATCH * N_HEAD), 256, ATTN_SMEM_FLOATS * 4>>>();

    split_kernel<<<n4x / 256, 256>>>(z, zh, zl, n4x);
    gemm_tc<false, true><<<ggrid, 256, GEMM_SMEM>>>(zh, zl, woh, wol, nullptr, x, out);
}

// round 15
// speedup vs baseline: 3.3511x; 1.2325x over previous
#include <cuda_runtime.h>
#include <cuda_bf16.h>
#include <math.h>
#include <stdint.h>

#define D_MODEL 1024
#define N_HEAD  16
#define D_HEAD  64
#define N_CTX   2048
#define BATCH   2
#define M_TOTAL (BATCH * N_CTX)   /* 4096 rows */

// fp32 scratch (QKV projection outputs)
__device__ float g_q[(size_t)M_TOTAL * D_MODEL];
__device__ float g_k[(size_t)M_TOTAL * D_MODEL];
__device__ float g_v[(size_t)M_TOTAL * D_MODEL];
__device__ float g_cos[N_CTX * 32];
__device__ float g_sin[N_CTX * 32];

// bf16 split scratch
__device__ __nv_bfloat16 g_xh[(size_t)M_TOTAL * D_MODEL];
__device__ __nv_bfloat16 g_xl[(size_t)M_TOTAL * D_MODEL];
__device__ __nv_bfloat16 g_zh[(size_t)M_TOTAL * D_MODEL];
__device__ __nv_bfloat16 g_zl[(size_t)M_TOTAL * D_MODEL];
__device__ __nv_bfloat16 g_qh[(size_t)M_TOTAL * D_MODEL];
__device__ __nv_bfloat16 g_ql[(size_t)M_TOTAL * D_MODEL];
__device__ __nv_bfloat16 g_kh[(size_t)M_TOTAL * D_MODEL];
__device__ __nv_bfloat16 g_kl[(size_t)M_TOTAL * D_MODEL];
__device__ __nv_bfloat16 g_vth[(size_t)D_MODEL * M_TOTAL];  // V^T [1024][4096]
__device__ __nv_bfloat16 g_vtl[(size_t)D_MODEL * M_TOTAL];
__device__ __nv_bfloat16 g_wqh[(size_t)D_MODEL * D_MODEL];
__device__ __nv_bfloat16 g_wql[(size_t)D_MODEL * D_MODEL];
__device__ __nv_bfloat16 g_wkh[(size_t)D_MODEL * D_MODEL];
__device__ __nv_bfloat16 g_wkl[(size_t)D_MODEL * D_MODEL];
__device__ __nv_bfloat16 g_wvh[(size_t)D_MODEL * D_MODEL];
__device__ __nv_bfloat16 g_wvl[(size_t)D_MODEL * D_MODEL];
__device__ __nv_bfloat16 g_woh[(size_t)D_MODEL * D_MODEL];
__device__ __nv_bfloat16 g_wol[(size_t)D_MODEL * D_MODEL];

// ---------------------------------------------------------------------------
// helpers
// ---------------------------------------------------------------------------
__device__ __forceinline__ uint32_t smem_u32(const void* p) {
    uint32_t a;
    asm("{ .reg .u64 t; cvta.to.shared.u64 t, %1; cvt.u32.u64 %0, t; }"
        : "=r"(a) : "l"(p));
    return a;
}

__device__ __forceinline__ void mma_bf16(float* c, uint32_t a0, uint32_t a1,
                                         uint32_t a2, uint32_t a3,
                                         uint32_t b0, uint32_t b1) {
    asm volatile(
        "mma.sync.aligned.m16n8k16.row.col.f32.bf16.bf16.f32 "
        "{%0,%1,%2,%3}, {%4,%5,%6,%7}, {%8,%9}, {%0,%1,%2,%3};"
        : "+f"(c[0]), "+f"(c[1]), "+f"(c[2]), "+f"(c[3])
        : "r"(a0), "r"(a1), "r"(a2), "r"(a3), "r"(b0), "r"(b1));
}

__device__ __forceinline__ uint32_t pack2(__nv_bfloat16 a, __nv_bfloat16 b) {
    __nv_bfloat162 t = __halves2bfloat162(a, b);   // a -> low half
    return *reinterpret_cast<uint32_t*>(&t);
}

// ---------------------------------------------------------------------------
// RoPE table: fp64 trig of the fp32-rounded angle (fast-math-proof).
// ---------------------------------------------------------------------------
__global__ void rope_table_kernel()
{
    int j = threadIdx.x;
    int s = blockIdx.x;
    float inv_freq = (float)pow(10000.0, -(double)j / 32.0);
    float a = (float)s * inv_freq;
    double sd, cd;
    sincos((double)a, &sd, &cd);
    g_cos[s * 32 + j] = (float)cd;
    g_sin[s * 32 + j] = (float)sd;
}

// ---------------------------------------------------------------------------
// fp32 -> (bf16 hi, bf16 lo) split.  n4 = element count / 4.
// ---------------------------------------------------------------------------
__global__ void __launch_bounds__(256)
split_kernel(const float* __restrict__ s, __nv_bfloat16* __restrict__ hi,
             __nv_bfloat16* __restrict__ lo, int n4)
{
    int i = blockIdx.x * 256 + threadIdx.x;
    if (i >= n4) return;
    float4 xv = ((const float4*)s)[i];
    float xs[4] = {xv.x, xv.y, xv.z, xv.w};
    __nv_bfloat16 h[4], l[4];
    #pragma unroll
    for (int j = 0; j < 4; j++) {
        h[j] = __float2bfloat16_rn(xs[j]);
        l[j] = __float2bfloat16_rn(xs[j] - __bfloat162float(h[j]));
    }
    ((__nv_bfloat162*)hi)[2*i+0] = __nv_bfloat162(h[0], h[1]);
    ((__nv_bfloat162*)hi)[2*i+1] = __nv_bfloat162(h[2], h[3]);
    ((__nv_bfloat162*)lo)[2*i+0] = __nv_bfloat162(l[0], l[1]);
    ((__nv_bfloat162*)lo)[2*i+1] = __nv_bfloat162(l[2], l[3]);
}

// ---------------------------------------------------------------------------
// V transpose + split: g_v [4096][1024] fp32 -> g_vth/g_vtl [1024][4096] bf16
// ---------------------------------------------------------------------------
__global__ void __launch_bounds__(256)
vtrans_kernel()
{
    __shared__ float t[32][33];
    const int tid = threadIdx.x;
    const int lr  = tid >> 3;          // 0..31
    const int lc4 = (tid & 7) * 4;     // 0..28
    const int c0  = blockIdx.x * 32;   // d cols   (0..1023)
    const int r0  = blockIdx.y * 32;   // m rows   (0..4095)

    float4 vv = *(const float4*)&g_v[(size_t)(r0 + lr) * D_MODEL + c0 + lc4];
    t[lc4+0][lr] = vv.x; t[lc4+1][lr] = vv.y;
    t[lc4+2][lr] = vv.z; t[lc4+3][lr] = vv.w;
    __syncthreads();

    // out row d = c0+lr, cols m = r0+lc4..+3
    __nv_bfloat16 h[4], l[4];
    #pragma unroll
    for (int j = 0; j < 4; j++) {
        float p = t[lr][lc4 + j];
        h[j] = __float2bfloat16_rn(p);
        l[j] = __float2bfloat16_rn(p - __bfloat162float(h[j]));
    }
    size_t ob = (size_t)(c0 + lr) * M_TOTAL + r0 + lc4;
    *(__nv_bfloat162*)&g_vth[ob]     = __nv_bfloat162(h[0], h[1]);
    *(__nv_bfloat162*)&g_vth[ob + 2] = __nv_bfloat162(h[2], h[3]);
    *(__nv_bfloat162*)&g_vtl[ob]     = __nv_bfloat162(l[0], l[1]);
    *(__nv_bfloat162*)&g_vtl[ob + 2] = __nv_bfloat162(l[2], l[3]);
}

// ---------------------------------------------------------------------------
// Tensor-core NT GEMM via mma.sync (unchanged R13 winner).
// ---------------------------------------------------------------------------
#define KC        32
#define TSTRIDE   40
#define TILE_ELS  (128 * TSTRIDE)
#define BUF_ELS   (4 * TILE_ELS)
#define GEMM_SMEM (2 * BUF_ELS * 2)

template <bool HAS_BIAS, bool HAS_ADD>
__global__ void __launch_bounds__(256)
gemm_tc(const __nv_bfloat16* __restrict__ Ah, const __nv_bfloat16* __restrict__ Al,
        const __nv_bfloat16* __restrict__ Bh, const __nv_bfloat16* __restrict__ Bl,
        const float* __restrict__ bias, const float* __restrict__ add,
        float* __restrict__ C)
{
    extern __shared__ __nv_bfloat16 sm[];
    const int tid = threadIdx.x;
    const int wid = tid >> 5;
    const int lane = tid & 31;
    const int g   = lane >> 2;
    const int tig = lane & 3;
    const int wm  = (wid & 1) * 64;
    const int wn  = (wid >> 1) * 32;
    const int n0  = blockIdx.x * 128;
    const int m0  = blockIdx.y * 128;
    const int K   = D_MODEL;

    #define ISSUE_TILE(SRC, RB, BASE, CH) do {                                 \
        _Pragma("unroll")                                                      \
        for (int it = 0; it < 2; it++) {                                       \
            int idx  = it * 256 + tid;                                         \
            int row  = idx >> 2;                                               \
            int col8 = (idx & 3) * 8;                                          \
            uint32_t daddr = smem_u32(&sm[(BASE) + row * TSTRIDE + col8]);     \
            const __nv_bfloat16* src = (SRC) + (size_t)((RB) + row) * K        \
                                       + (CH) * KC + col8;                     \
            asm volatile("cp.async.cg.shared.global [%0], [%1], 16;"           \
                         :: "r"(daddr), "l"(src));                             \
        }                                                                      \
    } while (0)

    #define ISSUE_CHUNK(CH, BUF) do {                                         \
        const int bb = (BUF) * BUF_ELS;                                       \
        ISSUE_TILE(Ah, m0, bb + 0 * TILE_ELS, CH);                            \
        ISSUE_TILE(Al, m0, bb + 1 * TILE_ELS, CH);                            \
        ISSUE_TILE(Bh, n0, bb + 2 * TILE_ELS, CH);                            \
        ISSUE_TILE(Bl, n0, bb + 3 * TILE_ELS, CH);                            \
        asm volatile("cp.async.commit_group;" ::: "memory");                  \
    } while (0)

    float acc[4][4][4] = {};

    ISSUE_CHUNK(0, 0);

    const int NCH = K / KC;
    for (int c = 0; c < NCH; c++) {
        const int buf = c & 1;
        if (c + 1 < NCH) {
            ISSUE_CHUNK(c + 1, buf ^ 1);
            asm volatile("cp.async.wait_group 1;" ::: "memory");
        } else {
            asm volatile("cp.async.wait_group 0;" ::: "memory");
        }
        __syncthreads();

        const int bb  = buf * BUF_ELS;
        const int Ahb = bb,                Alb = bb + TILE_ELS;
        const int Whb = bb + 2 * TILE_ELS, Wlb = bb + 3 * TILE_ELS;

        #pragma unroll
        for (int ks = 0; ks < KC; ks += 16) {
            uint32_t bh[4][2], bl[4][2];
            #pragma unroll
            for (int fn = 0; fn < 4; fn++) {
                int rn = (wn + fn * 8 + g) * TSTRIDE + ks + tig * 2;
                bh[fn][0] = *(const uint32_t*)&sm[Whb + rn];
                bh[fn][1] = *(const uint32_t*)&sm[Whb + rn + 8];
                bl[fn][0] = *(const uint32_t*)&sm[Wlb + rn];
                bl[fn][1] = *(const uint32_t*)&sm[Wlb + rn + 8];
            }
            #pragma unroll
            for (int fm = 0; fm < 4; fm++) {
                int r0 = (wm + fm * 16 + g) * TSTRIDE + ks + tig * 2;
                int r8 = r0 + 8 * TSTRIDE;
                uint32_t ah0 = *(const uint32_t*)&sm[Ahb + r0];
                uint32_t ah1 = *(const uint32_t*)&sm[Ahb + r8];
                uint32_t ah2 = *(const uint32_t*)&sm[Ahb + r0 + 8];
                uint32_t ah3 = *(const uint32_t*)&sm[Ahb + r8 + 8];
                uint32_t al0 = *(const uint32_t*)&sm[Alb + r0];
                uint32_t al1 = *(const uint32_t*)&sm[Alb + r8];
                uint32_t al2 = *(const uint32_t*)&sm[Alb + r0 + 8];
                uint32_t al3 = *(const uint32_t*)&sm[Alb + r8 + 8];
                #pragma unroll
                for (int fn = 0; fn < 4; fn++) {
                    mma_bf16(acc[fm][fn], ah0, ah1, ah2, ah3, bh[fn][0], bh[fn][1]);
                    mma_bf16(acc[fm][fn], ah0, ah1, ah2, ah3, bl[fn][0], bl[fn][1]);
                    mma_bf16(acc[fm][fn], al0, al1, al2, al3, bh[fn][0], bh[fn][1]);
                }
            }
        }
        __syncthreads();
    }
    #undef ISSUE_CHUNK
    #undef ISSUE_TILE

    #pragma unroll
    for (int fm = 0; fm < 4; fm++) {
        #pragma unroll
        for (int fn = 0; fn < 4; fn++) {
            const int col = n0 + wn + fn * 8 + tig * 2;
            float bx = 0.f, by = 0.f;
            if (HAS_BIAS) { bx = bias[col]; by = bias[col + 1]; }
            #pragma unroll
            for (int hrow = 0; hrow < 2; hrow++) {
                const int row = m0 + wm + fm * 16 + g + hrow * 8;
                float ox = acc[fm][fn][hrow * 2 + 0] + bx;
                float oy = acc[fm][fn][hrow * 2 + 1] + by;
                if (HAS_ADD) {
                    float2 av = *(const float2*)&add[(size_t)row * D_MODEL + col];
                    ox += av.x; oy += av.y;
                }
                *(float2*)&C[(size_t)row * D_MODEL + col] = make_float2(ox, oy);
            }
        }
    }
}

// ---------------------------------------------------------------------------
// RMSNorm + RoPE; reads fp32 proj output, writes bf16 hi/lo split.
// ---------------------------------------------------------------------------
__global__ void __launch_bounds__(256)
norm_rope_kernel(const float* __restrict__ in, __nv_bfloat16* __restrict__ oh,
                 __nv_bfloat16* __restrict__ ol, const float* __restrict__ norm_w)
{
    int gwarp = (blockIdx.x * blockDim.x + threadIdx.x) >> 5;
    int lane  = threadIdx.x & 31;
    if (gwarp >= M_TOTAL * N_HEAD) return;

    int m = gwarp >> 4;
    int h = gwarp & 15;
    int s = m & (N_CTX - 1);

    const float* p = in + (size_t)m * D_MODEL + h * D_HEAD;
    float2 x = *(const float2*)(p + 2 * lane);

    float ss = x.x * x.x + x.y * x.y;
    #pragma unroll
    for (int off = 16; off > 0; off >>= 1)
        ss += __shfl_xor_sync(0xFFFFFFFFu, ss, off);

    float r = rsqrtf(ss * (1.0f / 64.0f) + 1.1920929e-07f);

    int d0 = 2 * lane, d1 = 2 * lane + 1;
    float xn0 = x.x * r * norm_w[d0];
    float xn1 = x.y * r * norm_w[d1];

    int j0 = d0 & 31, j1 = d1 & 31;
    float c0 = g_cos[s * 32 + j0], s0 = g_sin[s * 32 + j0];
    float c1 = g_cos[s * 32 + j1], s1 = g_sin[s * 32 + j1];

    float o0 = xn0 * c0 - xn1 * s0;
    float o1 = xn1 * c1 + xn0 * s1;

    __nv_bfloat16 h0 = __float2bfloat16_rn(o0);
    __nv_bfloat16 h1 = __float2bfloat16_rn(o1);
    __nv_bfloat16 l0 = __float2bfloat16_rn(o0 - __bfloat162float(h0));
    __nv_bfloat16 l1 = __float2bfloat16_rn(o1 - __bfloat162float(h1));

    size_t ob = (size_t)m * D_MODEL + h * D_HEAD + 2 * lane;
    *(__nv_bfloat162*)&oh[ob] = __nv_bfloat162(h0, h1);
    *(__nv_bfloat162*)&ol[ob] = __nv_bfloat162(l0, l1);
}

// ---------------------------------------------------------------------------
// HMMA quadratic attention: z[q,:] = sum_{k<=q} (q.k/64)^2 * v[k,:]
// CTA: 128 q-rows x one (b,h); k-tiles of 64; 8 warps x m16.
// Q in registers; P re-packed from S C-frags to A-frags (no smem round trip).
// bf16x3 split throughout. Writes zh/zl directly.
// ---------------------------------------------------------------------------
#define AST       72                         /* smem row stride (bf16 elems) */
#define AT_QH     0
#define AT_QL     (128 * AST)                /* 9216 */
#define AT_KV     (2 * 128 * AST)            /* 18432 */
#define AT_TILE   (64 * AST)                 /* 4608 */
#define AT_BUF    (4 * AT_TILE)              /* 18432 */
#define ATTN_SMEM_BYTES ((AT_KV + 2 * AT_BUF) * 2)   /* 110592 */

__global__ void __launch_bounds__(256, 1)
attn_mma()
{
    extern __shared__ __nv_bfloat16 sma[];
    const int tid  = threadIdx.x;
    const int wid  = tid >> 5;
    const int lane = tid & 31;
    const int g    = lane >> 2;
    const int tig  = lane & 3;
    const int qi   = (N_CTX / 128 - 1) - (int)blockIdx.x;   // heavy first
    const int bh   = blockIdx.y;
    const int b    = bh >> 4;
    const int h    = bh & 15;
    const int q0   = qi * 128;
    const int nkt  = 2 * qi + 2;

    const __nv_bfloat16* Qhg = g_qh + (size_t)(b * N_CTX + q0) * D_MODEL + h * 64;
    const __nv_bfloat16* Qlg = g_ql + (size_t)(b * N_CTX + q0) * D_MODEL + h * 64;
    const __nv_bfloat16* Khg = g_kh + (size_t)(b * N_CTX) * D_MODEL + h * 64;
    const __nv_bfloat16* Klg = g_kl + (size_t)(b * N_CTX) * D_MODEL + h * 64;
    const __nv_bfloat16* Vhg = g_vth + (size_t)(h * 64) * M_TOTAL + b * N_CTX;
    const __nv_bfloat16* Vlg = g_vtl + (size_t)(h * 64) * M_TOTAL + b * N_CTX;

    // ---- issue Q load (group 0) ----
    #pragma unroll
    for (int it = 0; it < 4; it++) {
        int idx  = it * 256 + tid;       // 0..1023
        int row  = idx >> 3;             // 0..127
        int col8 = (idx & 7) * 8;
        uint32_t dh = smem_u32(&sma[AT_QH + row * AST + col8]);
        uint32_t dl = smem_u32(&sma[AT_QL + row * AST + col8]);
        asm volatile("cp.async.cg.shared.global [%0], [%1], 16;"
                     :: "r"(dh), "l"(Qhg + (size_t)row * D_MODEL + col8));
        asm volatile("cp.async.cg.shared.global [%0], [%1], 16;"
                     :: "r"(dl), "l"(Qlg + (size_t)row * D_MODEL + col8));
    }
    asm volatile("cp.async.commit_group;" ::: "memory");

    // KV tile issue macro (one group per tile)
    #define ISSUE_KV(KT, BUF) do {                                             \
        const int k0i = (KT) * 64;                                             \
        const int bb  = AT_KV + (BUF) * AT_BUF;                                \
        _Pragma("unroll")                                                      \
        for (int it = 0; it < 2; it++) {                                       \
            int idx  = it * 256 + tid;   /* 0..511 */                          \
            int row  = idx >> 3;         /* 0..63  */                          \
            int col8 = (idx & 7) * 8;                                          \
            uint32_t d0a = smem_u32(&sma[bb + 0*AT_TILE + row * AST + col8]);  \
            uint32_t d1a = smem_u32(&sma[bb + 1*AT_TILE + row * AST + col8]);  \
            uint32_t d2a = smem_u32(&sma[bb + 2*AT_TILE + row * AST + col8]);  \
            uint32_t d3a = smem_u32(&sma[bb + 3*AT_TILE + row * AST + col8]);  \
            asm volatile("cp.async.cg.shared.global [%0], [%1], 16;"           \
                :: "r"(d0a), "l"(Khg + (size_t)(k0i + row) * D_MODEL + col8)); \
            asm volatile("cp.async.cg.shared.global [%0], [%1], 16;"           \
                :: "r"(d1a), "l"(Klg + (size_t)(k0i + row) * D_MODEL + col8)); \
            asm volatile("cp.async.cg.shared.global [%0], [%1], 16;"           \
                :: "r"(d2a), "l"(Vhg + (size_t)row * M_TOTAL + k0i + col8));   \
            asm volatile("cp.async.cg.shared.global [%0], [%1], 16;"           \
                :: "r"(d3a), "l"(Vlg + (size_t)row * M_TOTAL + k0i + col8));   \
        }                                                                      \
        asm volatile("cp.async.commit_group;" ::: "memory");                   \
    } while (0)

    ISSUE_KV(0, 0);                                  // group 1
    asm volatile("cp.async.wait_group 1;" ::: "memory");   // Q ready
    __syncthreads();

    // ---- Q fragments into registers (validated GEMM A-frag pattern) ----
    uint32_t qa_h[4][4], qa_l[4][4];
    {
        const int qr = wid * 16 + g;
        #pragma unroll
        for (int ks = 0; ks < 4; ks++) {
            int r0 = qr * AST + ks * 16 + tig * 2;
            int r8 = r0 + 8 * AST;
            qa_h[ks][0] = *(const uint32_t*)&sma[AT_QH + r0];
            qa_h[ks][1] = *(const uint32_t*)&sma[AT_QH + r8];
            qa_h[ks][2] = *(const uint32_t*)&sma[AT_QH + r0 + 8];
            qa_h[ks][3] = *(const uint32_t*)&sma[AT_QH + r8 + 8];
            qa_l[ks][0] = *(const uint32_t*)&sma[AT_QL + r0];
            qa_l[ks][1] = *(const uint32_t*)&sma[AT_QL + r8];
            qa_l[ks][2] = *(const uint32_t*)&sma[AT_QL + r0 + 8];
            qa_l[ks][3] = *(const uint32_t*)&sma[AT_QL + r8 + 8];
        }
    }

    float zacc[8][4] = {};
    const int qg  = q0 + wid * 16 + g;     // this thread's q rows: qg, qg+8
    const int qg8 = qg + 8;

    for (int kt = 0; kt < nkt; kt++) {
        if (kt + 1 < nkt) {
            ISSUE_KV(kt + 1, (kt + 1) & 1);
            asm volatile("cp.async.wait_group 1;" ::: "memory");
        } else {
            asm volatile("cp.async.wait_group 0;" ::: "memory");
        }
        __syncthreads();

        const int  k0   = kt * 64;
        const bool diag = (kt >= 2 * qi);
        const bool act  = (k0 <= q0 + wid * 16 + 15);  // warp has unmasked rows
        const int  bb   = AT_KV + (kt & 1) * AT_BUF;
        const int  Khb  = bb,               Klb = bb + AT_TILE;
        const int  Vhb  = bb + 2 * AT_TILE, Vlb = bb + 3 * AT_TILE;

        if (act) {
            // ---- S = Q.K^T (bf16x3) ----
            float sacc[8][4] = {};
            #pragma unroll
            for (int ks = 0; ks < 4; ks++) {
                #pragma unroll
                for (int fn = 0; fn < 8; fn++) {
                    int rn = (fn * 8 + g) * AST + ks * 16 + tig * 2;
                    uint32_t kb0 = *(const uint32_t*)&sma[Khb + rn];
                    uint32_t kb1 = *(const uint32_t*)&sma[Khb + rn + 8];
                    uint32_t kl0 = *(const uint32_t*)&sma[Klb + rn];
                    uint32_t kl1 = *(const uint32_t*)&sma[Klb + rn + 8];
                    mma_bf16(sacc[fn], qa_h[ks][0], qa_h[ks][1], qa_h[ks][2],
                             qa_h[ks][3], kb0, kb1);
                    mma_bf16(sacc[fn], qa_h[ks][0], qa_h[ks][1], qa_h[ks][2],
                             qa_h[ks][3], kl0, kl1);
                    mma_bf16(sacc[fn], qa_l[ks][0], qa_l[ks][1], qa_l[ks][2],
                             qa_l[ks][3], kb0, kb1);
                }
            }

            // ---- P = (S/64)^2 masked; split; repack C-frags -> A-frags ----
            uint32_t pa_h[4][4], pa_l[4][4];
            #pragma unroll
            for (int fn = 0; fn < 8; fn++) {
                float p0 = sacc[fn][0] * 0.015625f; p0 *= p0;
                float p1 = sacc[fn][1] * 0.015625f; p1 *= p1;
                float p2 = sacc[fn][2] * 0.015625f; p2 *= p2;
                float p3 = sacc[fn][3] * 0.015625f; p3 *= p3;
                if (diag) {
                    int sb = k0 + fn * 8 + tig * 2;
                    if (sb     > qg ) p0 = 0.f;
                    if (sb + 1 > qg ) p1 = 0.f;
                    if (sb     > qg8) p2 = 0.f;
                    if (sb + 1 > qg8) p3 = 0.f;
                }
                __nv_bfloat16 h0 = __float2bfloat16_rn(p0);
                __nv_bfloat16 h1 = __float2bfloat16_rn(p1);
                __nv_bfloat16 h2 = __float2bfloat16_rn(p2);
                __nv_bfloat16 h3 = __float2bfloat16_rn(p3);
                __nv_bfloat16 l0 = __float2bfloat16_rn(p0 - __bfloat162float(h0));
                __nv_bfloat16 l1 = __float2bfloat16_rn(p1 - __bfloat162float(h1));
                __nv_bfloat16 l2 = __float2bfloat16_rn(p2 - __bfloat162float(h2));
                __nv_bfloat16 l3 = __float2bfloat16_rn(p3 - __bfloat162float(h3));
                pa_h[fn >> 1][(fn & 1) * 2 + 0] = pack2(h0, h1);  // a0/a2: row g
                pa_h[fn >> 1][(fn & 1) * 2 + 1] = pack2(h2, h3);  // a1/a3: row g+8
                pa_l[fn >> 1][(fn & 1) * 2 + 0] = pack2(l0, l1);
                pa_l[fn >> 1][(fn & 1) * 2 + 1] = pack2(l2, l3);
            }

            // ---- Z += P.V (bf16x3), B = Vt[d][s] ----
            #pragma unroll
            for (int ks = 0; ks < 4; ks++) {
                #pragma unroll
                for (int fn = 0; fn < 8; fn++) {
                    int rn = (fn * 8 + g) * AST + ks * 16 + tig * 2;
                    uint32_t vb0 = *(const uint32_t*)&sma[Vhb + rn];
                    uint32_t vb1 = *(const uint32_t*)&sma[Vhb + rn + 8];
                    uint32_t vl0 = *(const uint32_t*)&sma[Vlb + rn];
                    uint32_t vl1 = *(const uint32_t*)&sma[Vlb + rn + 8];
                    mma_bf16(zacc[fn], pa_h[ks][0], pa_h[ks][1], pa_h[ks][2],
                             pa_h[ks][3], vb0, vb1);
                    mma_bf16(zacc[fn], pa_h[ks][0], pa_h[ks][1], pa_h[ks][2],
                             pa_h[ks][3], vl0, vl1);
                    mma_bf16(zacc[fn], pa_l[ks][0], pa_l[ks][1], pa_l[ks][2],
                             pa_l[ks][3], vb0, vb1);
                }
            }
        }
        __syncthreads();
    }
    #undef ISSUE_KV

    // ---- epilogue: split z to bf16 hi/lo and store ----
    const size_t rowg  = (size_t)(b * N_CTX + qg)  * D_MODEL + h * 64;
    const size_t rowg8 = (size_t)(b * N_CTX + qg8) * D_MODEL + h * 64;
    #pragma unroll
    for (int fn = 0; fn < 8; fn++) {
        const int col = fn * 8 + tig * 2;
        float z0 = zacc[fn][0], z1 = zacc[fn][1];
        float z2 = zacc[fn][2], z3 = zacc[fn][3];
        __nv_bfloat16 h0 = __float2bfloat16_rn(z0);
        __nv_bfloat16 h1 = __float2bfloat16_rn(z1);
        __nv_bfloat16 h2 = __float2bfloat16_rn(z2);
        __nv_bfloat16 h3 = __float2bfloat16_rn(z3);
        __nv_bfloat16 l0 = __float2bfloat16_rn(z0 - __bfloat162float(h0));
        __nv_bfloat16 l1 = __float2bfloat16_rn(z1 - __bfloat162float(h1));
        __nv_bfloat16 l2 = __float2bfloat16_rn(z2 - __bfloat162float(h2));
        __nv_bfloat16 l3 = __float2bfloat16_rn(z3 - __bfloat162float(h3));
        *(__nv_bfloat162*)&g_zh[rowg  + col] = __nv_bfloat162(h0, h1);
        *(__nv_bfloat162*)&g_zh[rowg8 + col] = __nv_bfloat162(h2, h3);
        *(__nv_bfloat162*)&g_zl[rowg  + col] = __nv_bfloat162(l0, l1);
        *(__nv_bfloat162*)&g_zl[rowg8 + col] = __nv_bfloat162(l2, l3);
    }
}

// ---------------------------------------------------------------------------
// Launch
// ---------------------------------------------------------------------------
extern "C" void kernel_launch(void* const* d_in, const int* in_sizes, int n_in,
                              void* d_out, int out_size)
{
    const float* x      = (const float*)d_in[0];
    const float* Wq     = (const float*)d_in[1];
    const float* bq     = (const float*)d_in[2];
    const float* Wk     = (const float*)d_in[3];
    const float* bk     = (const float*)d_in[4];
    const float* Wv     = (const float*)d_in[5];
    const float* bv     = (const float*)d_in[6];
    const float* Wo     = (const float*)d_in[7];
    const float* norm_w = (const float*)d_in[8];
    float* out          = (float*)d_out;

    float *q, *k, *v;
    cudaGetSymbolAddress((void**)&q, g_q);
    cudaGetSymbolAddress((void**)&k, g_k);
    cudaGetSymbolAddress((void**)&v, g_v);

    __nv_bfloat16 *xh, *xl, *zh, *zl, *qh, *ql, *kh, *kl;
    __nv_bfloat16 *wqh, *wql, *wkh, *wkl, *wvh, *wvl, *woh, *wol;
    cudaGetSymbolAddress((void**)&xh,  g_xh);  cudaGetSymbolAddress((void**)&xl,  g_xl);
    cudaGetSymbolAddress((void**)&zh,  g_zh);  cudaGetSymbolAddress((void**)&zl,  g_zl);
    cudaGetSymbolAddress((void**)&qh,  g_qh);  cudaGetSymbolAddress((void**)&ql,  g_ql);
    cudaGetSymbolAddress((void**)&kh,  g_kh);  cudaGetSymbolAddress((void**)&kl,  g_kl);
    cudaGetSymbolAddress((void**)&wqh, g_wqh); cudaGetSymbolAddress((void**)&wql, g_wql);
    cudaGetSymbolAddress((void**)&wkh, g_wkh); cudaGetSymbolAddress((void**)&wkl, g_wkl);
    cudaGetSymbolAddress((void**)&wvh, g_wvh); cudaGetSymbolAddress((void**)&wvl, g_wvl);
    cudaGetSymbolAddress((void**)&woh, g_woh); cudaGetSymbolAddress((void**)&wol, g_wol);

    cudaFuncSetAttribute(gemm_tc<true, false>,
                         cudaFuncAttributeMaxDynamicSharedMemorySize, GEMM_SMEM);
    cudaFuncSetAttribute(gemm_tc<false, true>,
                         cudaFuncAttributeMaxDynamicSharedMemorySize, GEMM_SMEM);
    cudaFuncSetAttribute(attn_mma,
                         cudaFuncAttributeMaxDynamicSharedMemorySize, ATTN_SMEM_BYTES);

    rope_table_kernel<<<N_CTX, 32>>>();

    const int n4x = (M_TOTAL * D_MODEL) / 4;
    const int n4w = (D_MODEL * D_MODEL) / 4;
    split_kernel<<<n4x / 256, 256>>>(x,  xh,  xl,  n4x);
    split_kernel<<<n4w / 256, 256>>>(Wq, wqh, wql, n4w);
    split_kernel<<<n4w / 256, 256>>>(Wk, wkh, wkl, n4w);
    split_kernel<<<n4w / 256, 256>>>(Wv, wvh, wvl, n4w);
    split_kernel<<<n4w / 256, 256>>>(Wo, woh, wol, n4w);

    dim3 ggrid(D_MODEL / 128, M_TOTAL / 128);    // (8, 32)
    gemm_tc<true, false><<<ggrid, 256, GEMM_SMEM>>>(xh, xl, wqh, wql, bq, nullptr, q);
    gemm_tc<true, false><<<ggrid, 256, GEMM_SMEM>>>(xh, xl, wkh, wkl, bk, nullptr, k);
    gemm_tc<true, false><<<ggrid, 256, GEMM_SMEM>>>(xh, xl, wvh, wvl, bv, nullptr, v);

    int nblocks = (M_TOTAL * N_HEAD) / 8;
    norm_rope_kernel<<<nblocks, 256>>>(q, qh, ql, norm_w);
    norm_rope_kernel<<<nblocks, 256>>>(k, kh, kl, norm_w);
    vtrans_kernel<<<dim3(D_MODEL / 32, M_TOTAL / 32), 256>>>();

    attn_mma<<<dim3(N_CTX / 128, BATCH * N_HEAD), 256, ATTN_SMEM_BYTES>>>();

    gemm_tc<false, true><<<ggrid, 256, GEMM_SMEM>>>(zh, zl, woh, wol, nullptr, x, out);
}

// round 16
// speedup vs baseline: 4.6736x; 1.3946x over previous
#include <cuda_runtime.h>
#include <cuda_bf16.h>
#include <math.h>
#include <stdint.h>

#define D_MODEL 1024
#define N_HEAD  16
#define D_HEAD  64
#define N_CTX   2048
#define BATCH   2
#define M_TOTAL (BATCH * N_CTX)   /* 4096 rows */

// fp32 scratch (QKV projection outputs)
__device__ float g_q[(size_t)M_TOTAL * D_MODEL];
__device__ float g_k[(size_t)M_TOTAL * D_MODEL];
__device__ float g_v[(size_t)M_TOTAL * D_MODEL];
__device__ float g_cos[N_CTX * 32];
__device__ float g_sin[N_CTX * 32];

// bf16 split scratch
__device__ __nv_bfloat16 g_xh[(size_t)M_TOTAL * D_MODEL];
__device__ __nv_bfloat16 g_xl[(size_t)M_TOTAL * D_MODEL];
__device__ __nv_bfloat16 g_zh[(size_t)M_TOTAL * D_MODEL];
__device__ __nv_bfloat16 g_zl[(size_t)M_TOTAL * D_MODEL];
__device__ __nv_bfloat16 g_qh[(size_t)M_TOTAL * D_MODEL];
__device__ __nv_bfloat16 g_ql[(size_t)M_TOTAL * D_MODEL];
__device__ __nv_bfloat16 g_kh[(size_t)M_TOTAL * D_MODEL];
__device__ __nv_bfloat16 g_kl[(size_t)M_TOTAL * D_MODEL];
__device__ __nv_bfloat16 g_vth[(size_t)D_MODEL * M_TOTAL];  // V^T [1024][4096]
__device__ __nv_bfloat16 g_vtl[(size_t)D_MODEL * M_TOTAL];
__device__ __nv_bfloat16 g_wqh[(size_t)D_MODEL * D_MODEL];
__device__ __nv_bfloat16 g_wql[(size_t)D_MODEL * D_MODEL];
__device__ __nv_bfloat16 g_wkh[(size_t)D_MODEL * D_MODEL];
__device__ __nv_bfloat16 g_wkl[(size_t)D_MODEL * D_MODEL];
__device__ __nv_bfloat16 g_wvh[(size_t)D_MODEL * D_MODEL];
__device__ __nv_bfloat16 g_wvl[(size_t)D_MODEL * D_MODEL];
__device__ __nv_bfloat16 g_woh[(size_t)D_MODEL * D_MODEL];
__device__ __nv_bfloat16 g_wol[(size_t)D_MODEL * D_MODEL];

// ---------------------------------------------------------------------------
// helpers
// ---------------------------------------------------------------------------
__device__ __forceinline__ uint32_t smem_u32(const void* p) {
    uint32_t a;
    asm("{ .reg .u64 t; cvta.to.shared.u64 t, %1; cvt.u32.u64 %0, t; }"
        : "=r"(a) : "l"(p));
    return a;
}

__device__ __forceinline__ void mma_bf16(float* c, uint32_t a0, uint32_t a1,
                                         uint32_t a2, uint32_t a3,
                                         uint32_t b0, uint32_t b1) {
    asm volatile(
        "mma.sync.aligned.m16n8k16.row.col.f32.bf16.bf16.f32 "
        "{%0,%1,%2,%3}, {%4,%5,%6,%7}, {%8,%9}, {%0,%1,%2,%3};"
        : "+f"(c[0]), "+f"(c[1]), "+f"(c[2]), "+f"(c[3])
        : "r"(a0), "r"(a1), "r"(a2), "r"(a3), "r"(b0), "r"(b1));
}

// x4 ldmatrix: 4 independent 8x8 b16 tiles; lane L supplies the address of
// row (L&7) of tile (L>>3). reg i <- tile i.
__device__ __forceinline__ void ldsm_x4(uint32_t& r0, uint32_t& r1,
                                        uint32_t& r2, uint32_t& r3,
                                        uint32_t addr) {
    asm volatile("ldmatrix.sync.aligned.m8n8.x4.shared.b16 {%0,%1,%2,%3}, [%4];"
                 : "=r"(r0), "=r"(r1), "=r"(r2), "=r"(r3) : "r"(addr));
}

__device__ __forceinline__ uint32_t pack2(__nv_bfloat16 a, __nv_bfloat16 b) {
    __nv_bfloat162 t = __halves2bfloat162(a, b);   // a -> low half
    return *reinterpret_cast<uint32_t*>(&t);
}

// ---------------------------------------------------------------------------
// RoPE table: fp64 trig of the fp32-rounded angle (fast-math-proof).
// ---------------------------------------------------------------------------
__global__ void rope_table_kernel()
{
    int j = threadIdx.x;
    int s = blockIdx.x;
    float inv_freq = (float)pow(10000.0, -(double)j / 32.0);
    float a = (float)s * inv_freq;
    double sd, cd;
    sincos((double)a, &sd, &cd);
    g_cos[s * 32 + j] = (float)cd;
    g_sin[s * 32 + j] = (float)sd;
}

// ---------------------------------------------------------------------------
// fp32 -> (bf16 hi, bf16 lo) split.  n4 = element count / 4.
// ---------------------------------------------------------------------------
__global__ void __launch_bounds__(256)
split_kernel(const float* __restrict__ s, __nv_bfloat16* __restrict__ hi,
             __nv_bfloat16* __restrict__ lo, int n4)
{
    int i = blockIdx.x * 256 + threadIdx.x;
    if (i >= n4) return;
    float4 xv = ((const float4*)s)[i];
    float xs[4] = {xv.x, xv.y, xv.z, xv.w};
    __nv_bfloat16 h[4], l[4];
    #pragma unroll
    for (int j = 0; j < 4; j++) {
        h[j] = __float2bfloat16_rn(xs[j]);
        l[j] = __float2bfloat16_rn(xs[j] - __bfloat162float(h[j]));
    }
    ((__nv_bfloat162*)hi)[2*i+0] = __nv_bfloat162(h[0], h[1]);
    ((__nv_bfloat162*)hi)[2*i+1] = __nv_bfloat162(h[2], h[3]);
    ((__nv_bfloat162*)lo)[2*i+0] = __nv_bfloat162(l[0], l[1]);
    ((__nv_bfloat162*)lo)[2*i+1] = __nv_bfloat162(l[2], l[3]);
}

// ---------------------------------------------------------------------------
// V transpose + split: g_v [4096][1024] fp32 -> g_vth/g_vtl [1024][4096] bf16
// ---------------------------------------------------------------------------
__global__ void __launch_bounds__(256)
vtrans_kernel()
{
    __shared__ float t[32][33];
    const int tid = threadIdx.x;
    const int lr  = tid >> 3;          // 0..31
    const int lc4 = (tid & 7) * 4;     // 0..28
    const int c0  = blockIdx.x * 32;   // d cols   (0..1023)
    const int r0  = blockIdx.y * 32;   // m rows   (0..4095)

    float4 vv = *(const float4*)&g_v[(size_t)(r0 + lr) * D_MODEL + c0 + lc4];
    t[lc4+0][lr] = vv.x; t[lc4+1][lr] = vv.y;
    t[lc4+2][lr] = vv.z; t[lc4+3][lr] = vv.w;
    __syncthreads();

    __nv_bfloat16 h[4], l[4];
    #pragma unroll
    for (int j = 0; j < 4; j++) {
        float p = t[lr][lc4 + j];
        h[j] = __float2bfloat16_rn(p);
        l[j] = __float2bfloat16_rn(p - __bfloat162float(h[j]));
    }
    size_t ob = (size_t)(c0 + lr) * M_TOTAL + r0 + lc4;
    *(__nv_bfloat162*)&g_vth[ob]     = __nv_bfloat162(h[0], h[1]);
    *(__nv_bfloat162*)&g_vth[ob + 2] = __nv_bfloat162(h[2], h[3]);
    *(__nv_bfloat162*)&g_vtl[ob]     = __nv_bfloat162(l[0], l[1]);
    *(__nv_bfloat162*)&g_vtl[ob + 2] = __nv_bfloat162(l[2], l[3]);
}

// ---------------------------------------------------------------------------
// Tensor-core NT GEMM via mma.sync + ldmatrix.
// CTA 128x128, 8 warps (2x4), warp tile 64x32, K-chunks of 32, cp.async
// double buffer. Fragment loads via ldmatrix.x4 (hi/lo tiles fused).
// ---------------------------------------------------------------------------
#define KC        32
#define TSTRIDE   40
#define TILE_ELS  (128 * TSTRIDE)
#define BUF_ELS   (4 * TILE_ELS)
#define GEMM_SMEM (2 * BUF_ELS * 2)

template <bool HAS_BIAS, bool HAS_ADD>
__global__ void __launch_bounds__(256)
gemm_tc(const __nv_bfloat16* __restrict__ Ah, const __nv_bfloat16* __restrict__ Al,
        const __nv_bfloat16* __restrict__ Bh, const __nv_bfloat16* __restrict__ Bl,
        const float* __restrict__ bias, const float* __restrict__ add,
        float* __restrict__ C)
{
    extern __shared__ __nv_bfloat16 sm[];
    const int tid = threadIdx.x;
    const int wid = tid >> 5;
    const int lane = tid & 31;
    const int g   = lane >> 2;
    const int tig = lane & 3;
    const int wm  = (wid & 1) * 64;
    const int wn  = (wid >> 1) * 32;
    const int n0  = blockIdx.x * 128;
    const int m0  = blockIdx.y * 128;
    const int K   = D_MODEL;

    // ldmatrix lane roles
    const int lt = lane >> 3;          // tile index 0..3
    const int lr = lane & 7;           // row within tile

    #define ISSUE_TILE(SRC, RB, BASE, CH) do {                                 \
        _Pragma("unroll")                                                      \
        for (int it = 0; it < 2; it++) {                                       \
            int idx  = it * 256 + tid;                                         \
            int row  = idx >> 2;                                               \
            int col8 = (idx & 3) * 8;                                          \
            uint32_t daddr = smem_u32(&sm[(BASE) + row * TSTRIDE + col8]);     \
            const __nv_bfloat16* src = (SRC) + (size_t)((RB) + row) * K        \
                                       + (CH) * KC + col8;                     \
            asm volatile("cp.async.cg.shared.global [%0], [%1], 16;"           \
                         :: "r"(daddr), "l"(src));                             \
        }                                                                      \
    } while (0)

    #define ISSUE_CHUNK(CH, BUF) do {                                         \
        const int bb = (BUF) * BUF_ELS;                                       \
        ISSUE_TILE(Ah, m0, bb + 0 * TILE_ELS, CH);                            \
        ISSUE_TILE(Al, m0, bb + 1 * TILE_ELS, CH);                            \
        ISSUE_TILE(Bh, n0, bb + 2 * TILE_ELS, CH);                            \
        ISSUE_TILE(Bl, n0, bb + 3 * TILE_ELS, CH);                            \
        asm volatile("cp.async.commit_group;" ::: "memory");                  \
    } while (0)

    float acc[4][4][4] = {};

    ISSUE_CHUNK(0, 0);

    const int NCH = K / KC;
    for (int c = 0; c < NCH; c++) {
        const int buf = c & 1;
        if (c + 1 < NCH) {
            ISSUE_CHUNK(c + 1, buf ^ 1);
            asm volatile("cp.async.wait_group 1;" ::: "memory");
        } else {
            asm volatile("cp.async.wait_group 0;" ::: "memory");
        }
        __syncthreads();

        const int bb  = buf * BUF_ELS;
        const int Ahb = bb,                Alb = bb + TILE_ELS;
        const int Whb = bb + 2 * TILE_ELS, Wlb = bb + 3 * TILE_ELS;

        #pragma unroll
        for (int ks = 0; ks < KC; ks += 16) {
            // B frags: one ldmatrix.x4 per fn -> {bh0, bh1, bl0, bl1}
            // tiles: t0/t1 = Whb k+{0,8}; t2/t3 = Wlb k+{0,8}
            uint32_t bh[4][2], bl[4][2];
            const int wbase = (lt < 2) ? Whb : Wlb;
            const int bkoff = ks + (lt & 1) * 8;
            #pragma unroll
            for (int fn = 0; fn < 4; fn++) {
                ldsm_x4(bh[fn][0], bh[fn][1], bl[fn][0], bl[fn][1],
                        smem_u32(&sm[wbase + (wn + fn * 8 + lr) * TSTRIDE + bkoff]));
            }
            // A frags: tiles t0..t3 = rows +{0,8} x k +{0,8}
            const int arow  = (lt & 1) * 8 + lr;
            const int akoff = ks + (lt >> 1) * 8;
            #pragma unroll
            for (int fm = 0; fm < 4; fm++) {
                uint32_t ah0, ah1, ah2, ah3, al0, al1, al2, al3;
                const int rbase = (wm + fm * 16 + arow) * TSTRIDE + akoff;
                ldsm_x4(ah0, ah1, ah2, ah3, smem_u32(&sm[Ahb + rbase]));
                ldsm_x4(al0, al1, al2, al3, smem_u32(&sm[Alb + rbase]));
                #pragma unroll
                for (int fn = 0; fn < 4; fn++) {
                    mma_bf16(acc[fm][fn], ah0, ah1, ah2, ah3, bh[fn][0], bh[fn][1]);
                    mma_bf16(acc[fm][fn], ah0, ah1, ah2, ah3, bl[fn][0], bl[fn][1]);
                    mma_bf16(acc[fm][fn], al0, al1, al2, al3, bh[fn][0], bh[fn][1]);
                }
            }
        }
        __syncthreads();
    }
    #undef ISSUE_CHUNK
    #undef ISSUE_TILE

    #pragma unroll
    for (int fm = 0; fm < 4; fm++) {
        #pragma unroll
        for (int fn = 0; fn < 4; fn++) {
            const int col = n0 + wn + fn * 8 + tig * 2;
            float bx = 0.f, by = 0.f;
            if (HAS_BIAS) { bx = bias[col]; by = bias[col + 1]; }
            #pragma unroll
            for (int hrow = 0; hrow < 2; hrow++) {
                const int row = m0 + wm + fm * 16 + g + hrow * 8;
                float ox = acc[fm][fn][hrow * 2 + 0] + bx;
                float oy = acc[fm][fn][hrow * 2 + 1] + by;
                if (HAS_ADD) {
                    float2 av = *(const float2*)&add[(size_t)row * D_MODEL + col];
                    ox += av.x; oy += av.y;
                }
                *(float2*)&C[(size_t)row * D_MODEL + col] = make_float2(ox, oy);
            }
        }
    }
}

// ---------------------------------------------------------------------------
// RMSNorm + RoPE; reads fp32 proj output, writes bf16 hi/lo split.
// ---------------------------------------------------------------------------
__global__ void __launch_bounds__(256)
norm_rope_kernel(const float* __restrict__ in, __nv_bfloat16* __restrict__ oh,
                 __nv_bfloat16* __restrict__ ol, const float* __restrict__ norm_w)
{
    int gwarp = (blockIdx.x * blockDim.x + threadIdx.x) >> 5;
    int lane  = threadIdx.x & 31;
    if (gwarp >= M_TOTAL * N_HEAD) return;

    int m = gwarp >> 4;
    int h = gwarp & 15;
    int s = m & (N_CTX - 1);

    const float* p = in + (size_t)m * D_MODEL + h * D_HEAD;
    float2 x = *(const float2*)(p + 2 * lane);

    float ss = x.x * x.x + x.y * x.y;
    #pragma unroll
    for (int off = 16; off > 0; off >>= 1)
        ss += __shfl_xor_sync(0xFFFFFFFFu, ss, off);

    float r = rsqrtf(ss * (1.0f / 64.0f) + 1.1920929e-07f);

    int d0 = 2 * lane, d1 = 2 * lane + 1;
    float xn0 = x.x * r * norm_w[d0];
    float xn1 = x.y * r * norm_w[d1];

    int j0 = d0 & 31, j1 = d1 & 31;
    float c0 = g_cos[s * 32 + j0], s0 = g_sin[s * 32 + j0];
    float c1 = g_cos[s * 32 + j1], s1 = g_sin[s * 32 + j1];

    float o0 = xn0 * c0 - xn1 * s0;
    float o1 = xn1 * c1 + xn0 * s1;

    __nv_bfloat16 h0 = __float2bfloat16_rn(o0);
    __nv_bfloat16 h1 = __float2bfloat16_rn(o1);
    __nv_bfloat16 l0 = __float2bfloat16_rn(o0 - __bfloat162float(h0));
    __nv_bfloat16 l1 = __float2bfloat16_rn(o1 - __bfloat162float(h1));

    size_t ob = (size_t)m * D_MODEL + h * D_HEAD + 2 * lane;
    *(__nv_bfloat162*)&oh[ob] = __nv_bfloat162(h0, h1);
    *(__nv_bfloat162*)&ol[ob] = __nv_bfloat162(l0, l1);
}

// ---------------------------------------------------------------------------
// HMMA quadratic attention with ldmatrix fragment loads.
// CTA: 128 q-rows x one (b,h); k-tiles of 64; 8 warps x m16.
// ---------------------------------------------------------------------------
#define AST       72                         /* smem row stride (bf16 elems) */
#define AT_QH     0
#define AT_QL     (128 * AST)                /* 9216 */
#define AT_KV     (2 * 128 * AST)            /* 18432 */
#define AT_TILE   (64 * AST)                 /* 4608 */
#define AT_BUF    (4 * AT_TILE)              /* 18432 */
#define ATTN_SMEM_BYTES ((AT_KV + 2 * AT_BUF) * 2)   /* 110592 */

__global__ void __launch_bounds__(256, 1)
attn_mma()
{
    extern __shared__ __nv_bfloat16 sma[];
    const int tid  = threadIdx.x;
    const int wid  = tid >> 5;
    const int lane = tid & 31;
    const int g    = lane >> 2;
    const int tig  = lane & 3;
    const int qi   = (N_CTX / 128 - 1) - (int)blockIdx.x;   // heavy first
    const int bh   = blockIdx.y;
    const int b    = bh >> 4;
    const int h    = bh & 15;
    const int q0   = qi * 128;
    const int nkt  = 2 * qi + 2;

    // ldmatrix lane roles
    const int lt = lane >> 3;      // tile 0..3
    const int lr = lane & 7;       // row in tile

    const __nv_bfloat16* Qhg = g_qh + (size_t)(b * N_CTX + q0) * D_MODEL + h * 64;
    const __nv_bfloat16* Qlg = g_ql + (size_t)(b * N_CTX + q0) * D_MODEL + h * 64;
    const __nv_bfloat16* Khg = g_kh + (size_t)(b * N_CTX) * D_MODEL + h * 64;
    const __nv_bfloat16* Klg = g_kl + (size_t)(b * N_CTX) * D_MODEL + h * 64;
    const __nv_bfloat16* Vhg = g_vth + (size_t)(h * 64) * M_TOTAL + b * N_CTX;
    const __nv_bfloat16* Vlg = g_vtl + (size_t)(h * 64) * M_TOTAL + b * N_CTX;

    // ---- issue Q load (group 0) ----
    #pragma unroll
    for (int it = 0; it < 4; it++) {
        int idx  = it * 256 + tid;       // 0..1023
        int row  = idx >> 3;             // 0..127
        int col8 = (idx & 7) * 8;
        uint32_t dh = smem_u32(&sma[AT_QH + row * AST + col8]);
        uint32_t dl = smem_u32(&sma[AT_QL + row * AST + col8]);
        asm volatile("cp.async.cg.shared.global [%0], [%1], 16;"
                     :: "r"(dh), "l"(Qhg + (size_t)row * D_MODEL + col8));
        asm volatile("cp.async.cg.shared.global [%0], [%1], 16;"
                     :: "r"(dl), "l"(Qlg + (size_t)row * D_MODEL + col8));
    }
    asm volatile("cp.async.commit_group;" ::: "memory");

    #define ISSUE_KV(KT, BUF) do {                                             \
        const int k0i = (KT) * 64;                                             \
        const int bb  = AT_KV + (BUF) * AT_BUF;                                \
        _Pragma("unroll")                                                      \
        for (int it = 0; it < 2; it++) {                                       \
            int idx  = it * 256 + tid;   /* 0..511 */                          \
            int row  = idx >> 3;         /* 0..63  */                          \
            int col8 = (idx & 7) * 8;                                          \
            uint32_t d0a = smem_u32(&sma[bb + 0*AT_TILE + row * AST + col8]);  \
            uint32_t d1a = smem_u32(&sma[bb + 1*AT_TILE + row * AST + col8]);  \
            uint32_t d2a = smem_u32(&sma[bb + 2*AT_TILE + row * AST + col8]);  \
            uint32_t d3a = smem_u32(&sma[bb + 3*AT_TILE + row * AST + col8]);  \
            asm volatile("cp.async.cg.shared.global [%0], [%1], 16;"           \
                :: "r"(d0a), "l"(Khg + (size_t)(k0i + row) * D_MODEL + col8)); \
            asm volatile("cp.async.cg.shared.global [%0], [%1], 16;"           \
                :: "r"(d1a), "l"(Klg + (size_t)(k0i + row) * D_MODEL + col8)); \
            asm volatile("cp.async.cg.shared.global [%0], [%1], 16;"           \
                :: "r"(d2a), "l"(Vhg + (size_t)row * M_TOTAL + k0i + col8));   \
            asm volatile("cp.async.cg.shared.global [%0], [%1], 16;"           \
                :: "r"(d3a), "l"(Vlg + (size_t)row * M_TOTAL + k0i + col8));   \
        }                                                                      \
        asm volatile("cp.async.commit_group;" ::: "memory");                   \
    } while (0)

    ISSUE_KV(0, 0);                                        // group 1
    asm volatile("cp.async.wait_group 1;" ::: "memory");   // Q ready
    __syncthreads();

    // ---- Q fragments via ldmatrix (tiles: rows +{0,8} x k +{0,8}) ----
    uint32_t qa_h[4][4], qa_l[4][4];
    {
        const int qrow = wid * 16 + (lt & 1) * 8 + lr;
        const int koff = (lt >> 1) * 8;
        #pragma unroll
        for (int ks = 0; ks < 4; ks++) {
            const int rb = qrow * AST + ks * 16 + koff;
            ldsm_x4(qa_h[ks][0], qa_h[ks][1], qa_h[ks][2], qa_h[ks][3],
                    smem_u32(&sma[AT_QH + rb]));
            ldsm_x4(qa_l[ks][0], qa_l[ks][1], qa_l[ks][2], qa_l[ks][3],
                    smem_u32(&sma[AT_QL + rb]));
        }
    }

    float zacc[8][4] = {};
    const int qg  = q0 + wid * 16 + g;     // this thread's q rows: qg, qg+8
    const int qg8 = qg + 8;

    // B-frag ldmatrix lane constants: tiles t0/t1 = hi k+{0,8}; t2/t3 = lo
    const int bsel  = (lt < 2) ? 0 : AT_TILE;   // hi tile vs lo tile
    const int bkoff = (lt & 1) * 8;

    for (int kt = 0; kt < nkt; kt++) {
        if (kt + 1 < nkt) {
            ISSUE_KV(kt + 1, (kt + 1) & 1);
            asm volatile("cp.async.wait_group 1;" ::: "memory");
        } else {
            asm volatile("cp.async.wait_group 0;" ::: "memory");
        }
        __syncthreads();

        const int  k0   = kt * 64;
        const bool diag = (kt >= 2 * qi);
        const bool act  = (k0 <= q0 + wid * 16 + 15);
        const int  bb   = AT_KV + (kt & 1) * AT_BUF;
        const int  Kb   = bb + bsel;            // Khb or Klb per lane tile
        const int  Vb   = bb + 2 * AT_TILE + bsel;

        if (act) {
            // ---- S = Q.K^T (bf16x3) ----
            float sacc[8][4] = {};
            #pragma unroll
            for (int ks = 0; ks < 4; ks++) {
                #pragma unroll
                for (int fn = 0; fn < 8; fn++) {
                    uint32_t kb0, kb1, kl0, kl1;
                    ldsm_x4(kb0, kb1, kl0, kl1,
                            smem_u32(&sma[Kb + (fn * 8 + lr) * AST + ks * 16 + bkoff]));
                    mma_bf16(sacc[fn], qa_h[ks][0], qa_h[ks][1], qa_h[ks][2],
                             qa_h[ks][3], kb0, kb1);
                    mma_bf16(sacc[fn], qa_h[ks][0], qa_h[ks][1], qa_h[ks][2],
                             qa_h[ks][3], kl0, kl1);
                    mma_bf16(sacc[fn], qa_l[ks][0], qa_l[ks][1], qa_l[ks][2],
                             qa_l[ks][3], kb0, kb1);
                }
            }

            // ---- P = (S/64)^2 masked; split; repack C-frags -> A-frags ----
            uint32_t pa_h[4][4], pa_l[4][4];
            #pragma unroll
            for (int fn = 0; fn < 8; fn++) {
                float p0 = sacc[fn][0] * 0.015625f; p0 *= p0;
                float p1 = sacc[fn][1] * 0.015625f; p1 *= p1;
                float p2 = sacc[fn][2] * 0.015625f; p2 *= p2;
                float p3 = sacc[fn][3] * 0.015625f; p3 *= p3;
                if (diag) {
                    int sb = k0 + fn * 8 + tig * 2;
                    if (sb     > qg ) p0 = 0.f;
                    if (sb + 1 > qg ) p1 = 0.f;
                    if (sb     > qg8) p2 = 0.f;
                    if (sb + 1 > qg8) p3 = 0.f;
                }
                __nv_bfloat16 h0 = __float2bfloat16_rn(p0);
                __nv_bfloat16 h1 = __float2bfloat16_rn(p1);
                __nv_bfloat16 h2 = __float2bfloat16_rn(p2);
                __nv_bfloat16 h3 = __float2bfloat16_rn(p3);
                __nv_bfloat16 l0 = __float2bfloat16_rn(p0 - __bfloat162float(h0));
                __nv_bfloat16 l1 = __float2bfloat16_rn(p1 - __bfloat162float(h1));
                __nv_bfloat16 l2 = __float2bfloat16_rn(p2 - __bfloat162float(h2));
                __nv_bfloat16 l3 = __float2bfloat16_rn(p3 - __bfloat162float(h3));
                pa_h[fn >> 1][(fn & 1) * 2 + 0] = pack2(h0, h1);
                pa_h[fn >> 1][(fn & 1) * 2 + 1] = pack2(h2, h3);
                pa_l[fn >> 1][(fn & 1) * 2 + 0] = pack2(l0, l1);
                pa_l[fn >> 1][(fn & 1) * 2 + 1] = pack2(l2, l3);
            }

            // ---- Z += P.V (bf16x3) ----
            #pragma unroll
            for (int ks = 0; ks < 4; ks++) {
                #pragma unroll
                for (int fn = 0; fn < 8; fn++) {
                    uint32_t vb0, vb1, vl0, vl1;
                    ldsm_x4(vb0, vb1, vl0, vl1,
                            smem_u32(&sma[Vb + (fn * 8 + lr) * AST + ks * 16 + bkoff]));
                    mma_bf16(zacc[fn], pa_h[ks][0], pa_h[ks][1], pa_h[ks][2],
                             pa_h[ks][3], vb0, vb1);
                    mma_bf16(zacc[fn], pa_h[ks][0], pa_h[ks][1], pa_h[ks][2],
                             pa_h[ks][3], vl0, vl1);
                    mma_bf16(zacc[fn], pa_l[ks][0], pa_l[ks][1], pa_l[ks][2],
                             pa_l[ks][3], vb0, vb1);
                }
            }
        }
        __syncthreads();
    }
    #undef ISSUE_KV

    // ---- epilogue: split z to bf16 hi/lo and store ----
    const size_t rowg  = (size_t)(b * N_CTX + qg)  * D_MODEL + h * 64;
    const size_t rowg8 = (size_t)(b * N_CTX + qg8) * D_MODEL + h * 64;
    #pragma unroll
    for (int fn = 0; fn < 8; fn++) {
        const int col = fn * 8 + tig * 2;
        float z0 = zacc[fn][0], z1 = zacc[fn][1];
        float z2 = zacc[fn][2], z3 = zacc[fn][3];
        __nv_bfloat16 h0 = __float2bfloat16_rn(z0);
        __nv_bfloat16 h1 = __float2bfloat16_rn(z1);
        __nv_bfloat16 h2 = __float2bfloat16_rn(z2);
        __nv_bfloat16 h3 = __float2bfloat16_rn(z3);
        __nv_bfloat16 l0 = __float2bfloat16_rn(z0 - __bfloat162float(h0));
        __nv_bfloat16 l1 = __float2bfloat16_rn(z1 - __bfloat162float(h1));
        __nv_bfloat16 l2 = __float2bfloat16_rn(z2 - __bfloat162float(h2));
        __nv_bfloat16 l3 = __float2bfloat16_rn(z3 - __bfloat162float(h3));
        *(__nv_bfloat162*)&g_zh[rowg  + col] = __nv_bfloat162(h0, h1);
        *(__nv_bfloat162*)&g_zh[rowg8 + col] = __nv_bfloat162(h2, h3);
        *(__nv_bfloat162*)&g_zl[rowg  + col] = __nv_bfloat162(l0, l1);
        *(__nv_bfloat162*)&g_zl[rowg8 + col] = __nv_bfloat162(l2, l3);
    }
}

// ---------------------------------------------------------------------------
// Launch
// ---------------------------------------------------------------------------
extern "C" void kernel_launch(void* const* d_in, const int* in_sizes, int n_in,
                              void* d_out, int out_size)
{
    const float* x      = (const float*)d_in[0];
    const float* Wq     = (const float*)d_in[1];
    const float* bq     = (const float*)d_in[2];
    const float* Wk     = (const float*)d_in[3];
    const float* bk     = (const float*)d_in[4];
    const float* Wv     = (const float*)d_in[5];
    const float* bv     = (const float*)d_in[6];
    const float* Wo     = (const float*)d_in[7];
    const float* norm_w = (const float*)d_in[8];
    float* out          = (float*)d_out;

    float *q, *k, *v;
    cudaGetSymbolAddress((void**)&q, g_q);
    cudaGetSymbolAddress((void**)&k, g_k);
    cudaGetSymbolAddress((void**)&v, g_v);

    __nv_bfloat16 *xh, *xl, *zh, *zl, *qh, *ql, *kh, *kl;
    __nv_bfloat16 *wqh, *wql, *wkh, *wkl, *wvh, *wvl, *woh, *wol;
    cudaGetSymbolAddress((void**)&xh,  g_xh);  cudaGetSymbolAddress((void**)&xl,  g_xl);
    cudaGetSymbolAddress((void**)&zh,  g_zh);  cudaGetSymbolAddress((void**)&zl,  g_zl);
    cudaGetSymbolAddress((void**)&qh,  g_qh);  cudaGetSymbolAddress((void**)&ql,  g_ql);
    cudaGetSymbolAddress((void**)&kh,  g_kh);  cudaGetSymbolAddress((void**)&kl,  g_kl);
    cudaGetSymbolAddress((void**)&wqh, g_wqh); cudaGetSymbolAddress((void**)&wql, g_wql);
    cudaGetSymbolAddress((void**)&wkh, g_wkh); cudaGetSymbolAddress((void**)&wkl, g_wkl);
    cudaGetSymbolAddress((void**)&wvh, g_wvh); cudaGetSymbolAddress((void**)&wvl, g_wvl);
    cudaGetSymbolAddress((void**)&woh, g_woh); cudaGetSymbolAddress((void**)&wol, g_wol);

    cudaFuncSetAttribute(gemm_tc<true, false>,
                         cudaFuncAttributeMaxDynamicSharedMemorySize, GEMM_SMEM);
    cudaFuncSetAttribute(gemm_tc<false, true>,
                         cudaFuncAttributeMaxDynamicSharedMemorySize, GEMM_SMEM);
    cudaFuncSetAttribute(attn_mma,
                         cudaFuncAttributeMaxDynamicSharedMemorySize, ATTN_SMEM_BYTES);

    rope_table_kernel<<<N_CTX, 32>>>();

    const int n4x = (M_TOTAL * D_MODEL) / 4;
    const int n4w = (D_MODEL * D_MODEL) / 4;
    split_kernel<<<n4x / 256, 256>>>(x,  xh,  xl,  n4x);
    split_kernel<<<n4w / 256, 256>>>(Wq, wqh, wql, n4w);
    split_kernel<<<n4w / 256, 256>>>(Wk, wkh, wkl, n4w);
    split_kernel<<<n4w / 256, 256>>>(Wv, wvh, wvl, n4w);
    split_kernel<<<n4w / 256, 256>>>(Wo, woh, wol, n4w);

    dim3 ggrid(D_MODEL / 128, M_TOTAL / 128);    // (8, 32)
    gemm_tc<true, false><<<ggrid, 256, GEMM_SMEM>>>(xh, xl, wqh, wql, bq, nullptr, q);
    gemm_tc<true, false><<<ggrid, 256, GEMM_SMEM>>>(xh, xl, wkh, wkl, bk, nullptr, k);
    gemm_tc<true, false><<<ggrid, 256, GEMM_SMEM>>>(xh, xl, wvh, wvl, bv, nullptr, v);

    int nblocks = (M_TOTAL * N_HEAD) / 8;
    norm_rope_kernel<<<nblocks, 256>>>(q, qh, ql, norm_w);
    norm_rope_kernel<<<nblocks, 256>>>(k, kh, kl, norm_w);
    vtrans_kernel<<<dim3(D_MODEL / 32, M_TOTAL / 32), 256>>>();

    attn_mma<<<dim3(N_CTX / 128, BATCH * N_HEAD), 256, ATTN_SMEM_BYTES>>>();

    gemm_tc<false, true><<<ggrid, 256, GEMM_SMEM>>>(zh, zl, woh, wol, nullptr, x, out);
}